// round 8
// baseline (speedup 1.0000x reference)
#include <cuda_runtime.h>
#include <cstdint>
#include <cmath>

// Problem constants (fixed by the reference)
#define D_MODEL   1024
#define NUM_HEADS 16
#define HEAD_DIM  64
#define B_SZ      2
#define SEQ       2048
#define M_TOT     (B_SZ * SEQ)   // 4096 rows for all projection GEMMs

// Scratch (allocation-free rule: __device__ globals). 4 x 16 MB = 64 MB.
__device__ float g_Q[(size_t)M_TOT * D_MODEL];
__device__ float g_K[(size_t)M_TOT * D_MODEL];
__device__ float g_V[(size_t)M_TOT * D_MODEL];
__device__ float g_C[(size_t)M_TOT * D_MODEL];

// ---------------------------------------------------------------------------
// tf32 helpers
// ---------------------------------------------------------------------------
__device__ __forceinline__ float f2tf32(float x) {
    asm("cvt.rna.tf32.f32 %0, %0;" : "+f"(x));
    return x;
}

__device__ __forceinline__ void mma_tf32(float& c0, float& c1, float& c2, float& c3,
                                         float a0, float a1, float a2, float a3,
                                         float b0, float b1)
{
    asm volatile(
        "mma.sync.aligned.m16n8k8.row.col.f32.tf32.tf32.f32 "
        "{%0,%1,%2,%3}, {%4,%5,%6,%7}, {%8,%9}, {%0,%1,%2,%3};\n"
        : "+f"(c0), "+f"(c1), "+f"(c2), "+f"(c3)
        : "r"(__float_as_uint(a0)), "r"(__float_as_uint(a1)),
          "r"(__float_as_uint(a2)), "r"(__float_as_uint(a3)),
          "r"(__float_as_uint(b0)), "r"(__float_as_uint(b1)));
}

// ---------------------------------------------------------------------------
// GEMM + bias (tf32 tensor cores):  Y[M,N] = X[M,K] @ W[K,N] + b[N]
// (unchanged — proven)
// ---------------------------------------------------------------------------
#define GPITCH 136

__global__ __launch_bounds__(256, 2) void gemm_tf32_kernel(
    const float* __restrict__ X, const float* __restrict__ W,
    const float* __restrict__ bias, float* __restrict__ Y,
    int M, int N, int K)
{
    __shared__ __align__(16) float As[2][16][GPITCH];   // As[buf][k][m]
    __shared__ __align__(16) float Bs[2][16][GPITCH];   // Bs[buf][k][n]

    const int tid  = threadIdx.x;
    const int lane = tid & 31;
    const int warp = tid >> 5;
    const int wm   = (warp >> 2) * 64;
    const int wn   = (warp & 3) * 32;
    const int r    = lane >> 2;
    const int c    = lane & 3;

    const int m0 = blockIdx.y * 128;
    const int n0 = blockIdx.x * 128;

    float acc[4][4][4];
    #pragma unroll
    for (int i = 0; i < 4; i++)
        #pragma unroll
        for (int j = 0; j < 4; j++)
            #pragma unroll
            for (int q = 0; q < 4; q++) acc[i][j][q] = 0.f;

    const int a_row = tid >> 1;
    const int a_kq  = (tid & 1) * 8;
    const int b_k   = tid >> 5;
    const int b_n4  = (tid & 31) * 4;

    const float* Xp = X + (size_t)(m0 + a_row) * K + a_kq;
    const float* Wp = W + (size_t)b_k * N + n0 + b_n4;

    float sa[8], sb[8];

    {
        float4 v0 = *(const float4*)(Xp + 0);
        float4 v1 = *(const float4*)(Xp + 4);
        sa[0]=v0.x; sa[1]=v0.y; sa[2]=v0.z; sa[3]=v0.w;
        sa[4]=v1.x; sa[5]=v1.y; sa[6]=v1.z; sa[7]=v1.w;
        float4 w0 = *(const float4*)(Wp);
        float4 w1 = *(const float4*)(Wp + (size_t)8 * N);
        sb[0]=w0.x; sb[1]=w0.y; sb[2]=w0.z; sb[3]=w0.w;
        sb[4]=w1.x; sb[5]=w1.y; sb[6]=w1.z; sb[7]=w1.w;
    }
    #pragma unroll
    for (int j = 0; j < 8; j++) As[0][a_kq + j][a_row] = f2tf32(sa[j]);
    {
        float4 t0 = make_float4(f2tf32(sb[0]), f2tf32(sb[1]), f2tf32(sb[2]), f2tf32(sb[3]));
        float4 t1 = make_float4(f2tf32(sb[4]), f2tf32(sb[5]), f2tf32(sb[6]), f2tf32(sb[7]));
        *(float4*)&Bs[0][b_k][b_n4]     = t0;
        *(float4*)&Bs[0][b_k + 8][b_n4] = t1;
    }
    __syncthreads();

    const int nIter = K / 16;
    for (int it = 0; it < nIter; it++) {
        const int buf = it & 1;

        if (it + 1 < nIter) {
            const int k0 = (it + 1) * 16;
            float4 v0 = *(const float4*)(Xp + k0);
            float4 v1 = *(const float4*)(Xp + k0 + 4);
            sa[0]=v0.x; sa[1]=v0.y; sa[2]=v0.z; sa[3]=v0.w;
            sa[4]=v1.x; sa[5]=v1.y; sa[6]=v1.z; sa[7]=v1.w;
            float4 w0 = *(const float4*)(Wp + (size_t)k0 * N);
            float4 w1 = *(const float4*)(Wp + (size_t)(k0 + 8) * N);
            sb[0]=w0.x; sb[1]=w0.y; sb[2]=w0.z; sb[3]=w0.w;
            sb[4]=w1.x; sb[5]=w1.y; sb[6]=w1.z; sb[7]=w1.w;
        }

        #pragma unroll
        for (int s = 0; s < 2; s++) {
            const int kb = s * 8;
            float af[4][4], bf[4][2];
            #pragma unroll
            for (int mi = 0; mi < 4; mi++) {
                const int mb = wm + 16 * mi;
                af[mi][0] = As[buf][kb + c    ][mb + r    ];
                af[mi][1] = As[buf][kb + c    ][mb + r + 8];
                af[mi][2] = As[buf][kb + c + 4][mb + r    ];
                af[mi][3] = As[buf][kb + c + 4][mb + r + 8];
            }
            #pragma unroll
            for (int ni = 0; ni < 4; ni++) {
                const int nb = wn + 8 * ni;
                bf[ni][0] = Bs[buf][kb + c    ][nb + r];
                bf[ni][1] = Bs[buf][kb + c + 4][nb + r];
            }
            #pragma unroll
            for (int mi = 0; mi < 4; mi++)
                #pragma unroll
                for (int ni = 0; ni < 4; ni++)
                    mma_tf32(acc[mi][ni][0], acc[mi][ni][1], acc[mi][ni][2], acc[mi][ni][3],
                             af[mi][0], af[mi][1], af[mi][2], af[mi][3],
                             bf[ni][0], bf[ni][1]);
        }

        if (it + 1 < nIter) {
            const int nb = (it + 1) & 1;
            #pragma unroll
            for (int j = 0; j < 8; j++) As[nb][a_kq + j][a_row] = f2tf32(sa[j]);
            float4 t0 = make_float4(f2tf32(sb[0]), f2tf32(sb[1]), f2tf32(sb[2]), f2tf32(sb[3]));
            float4 t1 = make_float4(f2tf32(sb[4]), f2tf32(sb[5]), f2tf32(sb[6]), f2tf32(sb[7]));
            *(float4*)&Bs[nb][b_k][b_n4]     = t0;
            *(float4*)&Bs[nb][b_k + 8][b_n4] = t1;
        }
        __syncthreads();
    }

    #pragma unroll
    for (int mi = 0; mi < 4; mi++) {
        const int m = m0 + wm + 16 * mi + r;
        #pragma unroll
        for (int ni = 0; ni < 4; ni++) {
            const int n = n0 + wn + 8 * ni + 2 * c;
            const float bx = bias[n], by = bias[n + 1];
            float2 o0 = make_float2(acc[mi][ni][0] + bx, acc[mi][ni][1] + by);
            float2 o1 = make_float2(acc[mi][ni][2] + bx, acc[mi][ni][3] + by);
            *(float2*)(Y + (size_t)m * N + n)       = o0;
            *(float2*)(Y + (size_t)(m + 8) * N + n) = o1;
        }
    }
}

// ---------------------------------------------------------------------------
// Flash attention, tf32 MMA, fragment-packed shared memory.
// CTA = (b, h, 128-row Q tile), 8 warps, warp strip = 16 Q rows, KTILE = 64.
//
// Packed layouts (lane = r*4+c, r=lane>>2, c=lane&3):
//  Qp[w][kk][lane]{4}: A-frag {Q[wq+r][8kk+c], Q[wq+r+8][8kk+c],
//                              Q[wq+r][8kk+c+4], Q[wq+r+8][8kk+c+4]}
//                      -> one LDS.128 per (warp,kk), conflict-free.
//  Kp[kk][nt][lane]{2}: B-frag {K[8nt+r][8kk+c], K[8nt+r][8kk+c+4]}
//                      + kk*4 skew -> one LDS.64, conflict-free.
//  Vp[kk][nt][lane]{2}: B-frag {V[8kk+c][8nt+r], V[8kk+c+4][8nt+r]}
//                      + kk*4 skew -> one LDS.64, conflict-free. (kk = seq chunk)
//  Ps: c-layout P round trip (pitch 68), warp-private rows.
// ---------------------------------------------------------------------------
#define QT      128
#define KTILE   64
#define KP      68

#define QP_OFF  0                      // 8*8*32*4      = 8192 floats
#define KP_OFF  8192                   // 8*8*32*2 + 7*4 + pad = 4128 floats
#define VP_OFF  (8192 + 4128)          // 4128 floats
#define PS_OFF  (8192 + 4128 + 4128)   // 128*68 = 8704 floats
#define ATTN_SMEM_FLOATS (PS_OFF + QT * KP)   // 25152 floats = 100608 B

__global__ __launch_bounds__(256, 2) void attn_mma_kernel(
    const float* __restrict__ Q, const float* __restrict__ K,
    const float* __restrict__ V, float* __restrict__ O)
{
    extern __shared__ __align__(16) float sm[];
    float* Qp = sm + QP_OFF;
    float* Kp = sm + KP_OFF;
    float* Vp = sm + VP_OFF;
    float* Ps = sm + PS_OFF;

    const int tid  = threadIdx.x;
    const int lane = tid & 31;
    const int warp = tid >> 5;
    const int r    = lane >> 2;   // 0..7
    const int c    = lane & 3;    // 0..3
    const int wq   = warp * 16;

    const int q0 = blockIdx.x * QT;
    const int h  = blockIdx.y;
    const int b  = blockIdx.z;
    const size_t base = (size_t)b * SEQ * D_MODEL + (size_t)h * HEAD_DIM;

    // ---- load Q tile (128 x 64) -> packed A-frag layout (once) ----
    #pragma unroll
    for (int i = 0; i < 8; i++) {
        const int idx  = i * 256 + tid;       // 2048 float4 slots
        const int row  = idx >> 4;            // 0..127
        const int col4 = (idx & 15) * 4;      // 0..60
        float4 v = *(const float4*)(Q + base + (size_t)(q0 + row) * D_MODEL + col4);
        const int w     = row >> 4;
        const int p     = row & 15;
        const int rr    = p & 7;
        const int jbase = (p >> 3) + ((col4 & 7) >> 2) * 2;  // rowhi + 2*colhi
        const int kk    = col4 >> 3;
        float* dst = Qp + ((w * 8 + kk) * 32 + rr * 4) * 4 + jbase;
        dst[0 * 4] = f2tf32(v.x);
        dst[1 * 4] = f2tf32(v.y);
        dst[2 * 4] = f2tf32(v.z);
        dst[3 * 4] = f2tf32(v.w);
    }

    float oacc[8][4];
    #pragma unroll
    for (int i = 0; i < 8; i++)
        #pragma unroll
        for (int j = 0; j < 4; j++) oacc[i][j] = 0.f;
    float m0v = -1e30f, m1v = -1e30f, l0 = 0.f, l1 = 0.f;

    const float scale = 0.125f;   // 1/sqrt(64)

    for (int kt = 0; kt < SEQ / KTILE; kt++) {
        __syncthreads();   // prev-iter consumers of Kp/Vp done; also covers Qp on iter 0

        // ---- stage K,V tiles (64 x 64) -> packed B-frag layouts ----
        #pragma unroll
        for (int i = 0; i < 4; i++) {
            const int idx  = i * 256 + tid;       // 1024 float4 slots
            const int row  = idx >> 4;            // 0..63
            const int col4 = (idx & 15) * 4;      // 0..60
            const size_t g = base + (size_t)(kt * KTILE + row) * D_MODEL + col4;

            // K[row][col]: nt=row>>3, r=row&7; kk=col>>3, slot=(col>>2)&1, c=col&3
            {
                float4 kv = *(const float4*)(K + g);
                const int nt   = row >> 3;
                const int rr   = row & 7;
                const int kk   = col4 >> 3;
                const int slot = (col4 >> 2) & 1;
                float* dst = Kp + ((kk * 8 + nt) * 32 + rr * 4) * 2 + slot + kk * 4;
                dst[0] = f2tf32(kv.x);
                dst[2] = f2tf32(kv.y);
                dst[4] = f2tf32(kv.z);
                dst[6] = f2tf32(kv.w);
            }
            // V[s][d]: s=row -> kk=s>>3, slot=((s&7)>>2), c=s&3; d -> nt=d>>3, r=d&7
            {
                float4 vv = *(const float4*)(V + g);
                const int kk   = row >> 3;
                const int cs   = row & 7;
                const int slot = cs >> 2;
                const int cc   = cs & 3;
                const int nt   = col4 >> 3;
                const int r0v  = col4 & 7;     // 0 or 4
                float* dst = Vp + ((kk * 8 + nt) * 32 + r0v * 4 + cc) * 2 + slot + kk * 4;
                dst[0 * 8] = f2tf32(vv.x);
                dst[1 * 8] = f2tf32(vv.y);
                dst[2 * 8] = f2tf32(vv.z);
                dst[3 * 8] = f2tf32(vv.w);
            }
        }
        __syncthreads();

        // ---- S = Q·K^T : one LDS.128 (A) + 8 LDS.64 (B) per kk ----
        float sacc[8][4];
        #pragma unroll
        for (int i = 0; i < 8; i++)
            #pragma unroll
            for (int j = 0; j < 4; j++) sacc[i][j] = 0.f;

        #pragma unroll
        for (int kk = 0; kk < 8; kk++) {
            float4 af = *(const float4*)&Qp[((warp * 8 + kk) * 32 + lane) * 4];
            #pragma unroll
            for (int nt = 0; nt < 8; nt++) {
                float2 bf = *(const float2*)&Kp[((kk * 8 + nt) * 32 + lane) * 2 + kk * 4];
                mma_tf32(sacc[nt][0], sacc[nt][1], sacc[nt][2], sacc[nt][3],
                         af.x, af.y, af.z, af.w, bf.x, bf.y);
            }
        }

        // ---- online softmax on fragments (rows r and r+8) ----
        float mx0 = -1e30f, mx1 = -1e30f;
        #pragma unroll
        for (int nt = 0; nt < 8; nt++) {
            sacc[nt][0] *= scale; sacc[nt][1] *= scale;
            sacc[nt][2] *= scale; sacc[nt][3] *= scale;
            mx0 = fmaxf(mx0, fmaxf(sacc[nt][0], sacc[nt][1]));
            mx1 = fmaxf(mx1, fmaxf(sacc[nt][2], sacc[nt][3]));
        }
        mx0 = fmaxf(mx0, __shfl_xor_sync(0xffffffffu, mx0, 1));
        mx0 = fmaxf(mx0, __shfl_xor_sync(0xffffffffu, mx0, 2));
        mx1 = fmaxf(mx1, __shfl_xor_sync(0xffffffffu, mx1, 1));
        mx1 = fmaxf(mx1, __shfl_xor_sync(0xffffffffu, mx1, 2));

        const float mn0 = fmaxf(m0v, mx0);
        const float mn1 = fmaxf(m1v, mx1);
        const float corr0 = __expf(m0v - mn0);
        const float corr1 = __expf(m1v - mn1);
        m0v = mn0; m1v = mn1;

        float rs0 = 0.f, rs1 = 0.f;
        #pragma unroll
        for (int nt = 0; nt < 8; nt++) {
            sacc[nt][0] = __expf(sacc[nt][0] - mn0);
            sacc[nt][1] = __expf(sacc[nt][1] - mn0);
            sacc[nt][2] = __expf(sacc[nt][2] - mn1);
            sacc[nt][3] = __expf(sacc[nt][3] - mn1);
            rs0 += sacc[nt][0] + sacc[nt][1];
            rs1 += sacc[nt][2] + sacc[nt][3];
        }
        rs0 += __shfl_xor_sync(0xffffffffu, rs0, 1);
        rs0 += __shfl_xor_sync(0xffffffffu, rs0, 2);
        rs1 += __shfl_xor_sync(0xffffffffu, rs1, 1);
        rs1 += __shfl_xor_sync(0xffffffffu, rs1, 2);

        l0 = l0 * corr0 + rs0;
        l1 = l1 * corr1 + rs1;
        #pragma unroll
        for (int nt = 0; nt < 8; nt++) {
            oacc[nt][0] *= corr0; oacc[nt][1] *= corr0;
            oacc[nt][2] *= corr1; oacc[nt][3] *= corr1;
        }

        // ---- write P to per-warp-private smem rows (accumulator layout) ----
        #pragma unroll
        for (int nt = 0; nt < 8; nt++) {
            float2 p0 = make_float2(f2tf32(sacc[nt][0]), f2tf32(sacc[nt][1]));
            float2 p1 = make_float2(f2tf32(sacc[nt][2]), f2tf32(sacc[nt][3]));
            *(float2*)&Ps[(wq + r    ) * KP + nt * 8 + 2 * c] = p0;
            *(float2*)&Ps[(wq + r + 8) * KP + nt * 8 + 2 * c] = p1;
        }
        __syncwarp();

        // ---- O += P·V : 4 scalar LDS (A) + 8 LDS.64 (B) per kk ----
        #pragma unroll
        for (int kk = 0; kk < 8; kk++) {
            const int kb = kk * 8;
            float a0 = Ps[(wq + r    ) * KP + kb + c    ];
            float a1 = Ps[(wq + r + 8) * KP + kb + c    ];
            float a2 = Ps[(wq + r    ) * KP + kb + c + 4];
            float a3 = Ps[(wq + r + 8) * KP + kb + c + 4];
            #pragma unroll
            for (int nt = 0; nt < 8; nt++) {
                float2 bf = *(const float2*)&Vp[((kk * 8 + nt) * 32 + lane) * 2 + kk * 4];
                mma_tf32(oacc[nt][0], oacc[nt][1], oacc[nt][2], oacc[nt][3],
                         a0, a1, a2, a3, bf.x, bf.y);
            }
        }
    }

    // ---- normalize and write context ----
    const float inv0 = 1.0f / l0;
    const float inv1 = 1.0f / l1;
    #pragma unroll
    for (int nt = 0; nt < 8; nt++) {
        const int col = nt * 8 + 2 * c;
        float2 o0 = make_float2(oacc[nt][0] * inv0, oacc[nt][1] * inv0);
        float2 o1 = make_float2(oacc[nt][2] * inv1, oacc[nt][3] * inv1);
        *(float2*)(O + base + (size_t)(q0 + wq + r    ) * D_MODEL + col) = o0;
        *(float2*)(O + base + (size_t)(q0 + wq + r + 8) * D_MODEL + col) = o1;
    }
}

// ---------------------------------------------------------------------------
// Launch: Q/K/V projections -> attention -> output projection
// Inputs (metadata order): x1, x2, Wq, bq, Wk, bk, Wv, bv, Wo, bo
// ---------------------------------------------------------------------------
extern "C" void kernel_launch(void* const* d_in, const int* in_sizes, int n_in,
                              void* d_out, int out_size)
{
    (void)in_sizes; (void)n_in; (void)out_size;

    const float* x1 = (const float*)d_in[0];
    const float* x2 = (const float*)d_in[1];
    const float* Wq = (const float*)d_in[2];
    const float* bq = (const float*)d_in[3];
    const float* Wk = (const float*)d_in[4];
    const float* bk = (const float*)d_in[5];
    const float* Wv = (const float*)d_in[6];
    const float* bv = (const float*)d_in[7];
    const float* Wo = (const float*)d_in[8];
    const float* bo = (const float*)d_in[9];
    float* out = (float*)d_out;

    float *Qp, *Kp, *Vp, *Cp;
    cudaGetSymbolAddress((void**)&Qp, g_Q);
    cudaGetSymbolAddress((void**)&Kp, g_K);
    cudaGetSymbolAddress((void**)&Vp, g_V);
    cudaGetSymbolAddress((void**)&Cp, g_C);

    const int attn_smem = ATTN_SMEM_FLOATS * (int)sizeof(float);   // 100608 B
    cudaFuncSetAttribute(attn_mma_kernel,
                         cudaFuncAttributeMaxDynamicSharedMemorySize, attn_smem);

    dim3 gemm_grid(D_MODEL / 128, M_TOT / 128);   // (8, 32)

    gemm_tf32_kernel<<<gemm_grid, 256>>>(x1, Wq, bq, Qp, M_TOT, D_MODEL, D_MODEL);
    gemm_tf32_kernel<<<gemm_grid, 256>>>(x2, Wk, bk, Kp, M_TOT, D_MODEL, D_MODEL);
    gemm_tf32_kernel<<<gemm_grid, 256>>>(x2, Wv, bv, Vp, M_TOT, D_MODEL, D_MODEL);

    dim3 attn_grid(SEQ / QT, NUM_HEADS, B_SZ);    // (16, 16, 2)
    attn_mma_kernel<<<attn_grid, 256, attn_smem>>>(Qp, Kp, Vp, Cp);

    gemm_tf32_kernel<<<gemm_grid, 256>>>(Cp, Wo, bo, out, M_TOT, D_MODEL, D_MODEL);
}

// round 9
// speedup vs baseline: 1.2547x; 1.2547x over previous
#include <cuda_runtime.h>
#include <cstdint>
#include <cmath>

// Problem constants (fixed by the reference)
#define D_MODEL   1024
#define NUM_HEADS 16
#define HEAD_DIM  64
#define B_SZ      2
#define SEQ       2048
#define M_TOT     (B_SZ * SEQ)   // 4096 rows for all projection GEMMs

// Scratch (allocation-free rule: __device__ globals). 4 x 16 MB = 64 MB.
__device__ float g_Q[(size_t)M_TOT * D_MODEL];
__device__ float g_K[(size_t)M_TOT * D_MODEL];
__device__ float g_V[(size_t)M_TOT * D_MODEL];
__device__ float g_C[(size_t)M_TOT * D_MODEL];

// ---------------------------------------------------------------------------
// tf32 helpers
// ---------------------------------------------------------------------------
__device__ __forceinline__ float f2tf32(float x) {
    asm("cvt.rna.tf32.f32 %0, %0;" : "+f"(x));
    return x;
}

__device__ __forceinline__ void mma_tf32(float& c0, float& c1, float& c2, float& c3,
                                         float a0, float a1, float a2, float a3,
                                         float b0, float b1)
{
    asm volatile(
        "mma.sync.aligned.m16n8k8.row.col.f32.tf32.tf32.f32 "
        "{%0,%1,%2,%3}, {%4,%5,%6,%7}, {%8,%9}, {%0,%1,%2,%3};\n"
        : "+f"(c0), "+f"(c1), "+f"(c2), "+f"(c3)
        : "r"(__float_as_uint(a0)), "r"(__float_as_uint(a1)),
          "r"(__float_as_uint(a2)), "r"(__float_as_uint(a3)),
          "r"(__float_as_uint(b0)), "r"(__float_as_uint(b1)));
}

// ---------------------------------------------------------------------------
// GEMM + bias (tf32 tensor cores):  Y[M,N] = X[M,K] @ W[K,N] + b[N]
// (unchanged — proven)
// ---------------------------------------------------------------------------
#define GPITCH 136

__global__ __launch_bounds__(256, 2) void gemm_tf32_kernel(
    const float* __restrict__ X, const float* __restrict__ W,
    const float* __restrict__ bias, float* __restrict__ Y,
    int M, int N, int K)
{
    __shared__ __align__(16) float As[2][16][GPITCH];   // As[buf][k][m]
    __shared__ __align__(16) float Bs[2][16][GPITCH];   // Bs[buf][k][n]

    const int tid  = threadIdx.x;
    const int lane = tid & 31;
    const int warp = tid >> 5;
    const int wm   = (warp >> 2) * 64;
    const int wn   = (warp & 3) * 32;
    const int r    = lane >> 2;
    const int c    = lane & 3;

    const int m0 = blockIdx.y * 128;
    const int n0 = blockIdx.x * 128;

    float acc[4][4][4];
    #pragma unroll
    for (int i = 0; i < 4; i++)
        #pragma unroll
        for (int j = 0; j < 4; j++)
            #pragma unroll
            for (int q = 0; q < 4; q++) acc[i][j][q] = 0.f;

    const int a_row = tid >> 1;
    const int a_kq  = (tid & 1) * 8;
    const int b_k   = tid >> 5;
    const int b_n4  = (tid & 31) * 4;

    const float* Xp = X + (size_t)(m0 + a_row) * K + a_kq;
    const float* Wp = W + (size_t)b_k * N + n0 + b_n4;

    float sa[8], sb[8];

    {
        float4 v0 = *(const float4*)(Xp + 0);
        float4 v1 = *(const float4*)(Xp + 4);
        sa[0]=v0.x; sa[1]=v0.y; sa[2]=v0.z; sa[3]=v0.w;
        sa[4]=v1.x; sa[5]=v1.y; sa[6]=v1.z; sa[7]=v1.w;
        float4 w0 = *(const float4*)(Wp);
        float4 w1 = *(const float4*)(Wp + (size_t)8 * N);
        sb[0]=w0.x; sb[1]=w0.y; sb[2]=w0.z; sb[3]=w0.w;
        sb[4]=w1.x; sb[5]=w1.y; sb[6]=w1.z; sb[7]=w1.w;
    }
    #pragma unroll
    for (int j = 0; j < 8; j++) As[0][a_kq + j][a_row] = f2tf32(sa[j]);
    {
        float4 t0 = make_float4(f2tf32(sb[0]), f2tf32(sb[1]), f2tf32(sb[2]), f2tf32(sb[3]));
        float4 t1 = make_float4(f2tf32(sb[4]), f2tf32(sb[5]), f2tf32(sb[6]), f2tf32(sb[7]));
        *(float4*)&Bs[0][b_k][b_n4]     = t0;
        *(float4*)&Bs[0][b_k + 8][b_n4] = t1;
    }
    __syncthreads();

    const int nIter = K / 16;
    for (int it = 0; it < nIter; it++) {
        const int buf = it & 1;

        if (it + 1 < nIter) {
            const int k0 = (it + 1) * 16;
            float4 v0 = *(const float4*)(Xp + k0);
            float4 v1 = *(const float4*)(Xp + k0 + 4);
            sa[0]=v0.x; sa[1]=v0.y; sa[2]=v0.z; sa[3]=v0.w;
            sa[4]=v1.x; sa[5]=v1.y; sa[6]=v1.z; sa[7]=v1.w;
            float4 w0 = *(const float4*)(Wp + (size_t)k0 * N);
            float4 w1 = *(const float4*)(Wp + (size_t)(k0 + 8) * N);
            sb[0]=w0.x; sb[1]=w0.y; sb[2]=w0.z; sb[3]=w0.w;
            sb[4]=w1.x; sb[5]=w1.y; sb[6]=w1.z; sb[7]=w1.w;
        }

        #pragma unroll
        for (int s = 0; s < 2; s++) {
            const int kb = s * 8;
            float af[4][4], bf[4][2];
            #pragma unroll
            for (int mi = 0; mi < 4; mi++) {
                const int mb = wm + 16 * mi;
                af[mi][0] = As[buf][kb + c    ][mb + r    ];
                af[mi][1] = As[buf][kb + c    ][mb + r + 8];
                af[mi][2] = As[buf][kb + c + 4][mb + r    ];
                af[mi][3] = As[buf][kb + c + 4][mb + r + 8];
            }
            #pragma unroll
            for (int ni = 0; ni < 4; ni++) {
                const int nb = wn + 8 * ni;
                bf[ni][0] = Bs[buf][kb + c    ][nb + r];
                bf[ni][1] = Bs[buf][kb + c + 4][nb + r];
            }
            #pragma unroll
            for (int mi = 0; mi < 4; mi++)
                #pragma unroll
                for (int ni = 0; ni < 4; ni++)
                    mma_tf32(acc[mi][ni][0], acc[mi][ni][1], acc[mi][ni][2], acc[mi][ni][3],
                             af[mi][0], af[mi][1], af[mi][2], af[mi][3],
                             bf[ni][0], bf[ni][1]);
        }

        if (it + 1 < nIter) {
            const int nb = (it + 1) & 1;
            #pragma unroll
            for (int j = 0; j < 8; j++) As[nb][a_kq + j][a_row] = f2tf32(sa[j]);
            float4 t0 = make_float4(f2tf32(sb[0]), f2tf32(sb[1]), f2tf32(sb[2]), f2tf32(sb[3]));
            float4 t1 = make_float4(f2tf32(sb[4]), f2tf32(sb[5]), f2tf32(sb[6]), f2tf32(sb[7]));
            *(float4*)&Bs[nb][b_k][b_n4]     = t0;
            *(float4*)&Bs[nb][b_k + 8][b_n4] = t1;
        }
        __syncthreads();
    }

    #pragma unroll
    for (int mi = 0; mi < 4; mi++) {
        const int m = m0 + wm + 16 * mi + r;
        #pragma unroll
        for (int ni = 0; ni < 4; ni++) {
            const int n = n0 + wn + 8 * ni + 2 * c;
            const float bx = bias[n], by = bias[n + 1];
            float2 o0 = make_float2(acc[mi][ni][0] + bx, acc[mi][ni][1] + by);
            float2 o1 = make_float2(acc[mi][ni][2] + bx, acc[mi][ni][3] + by);
            *(float2*)(Y + (size_t)m * N + n)       = o0;
            *(float2*)(Y + (size_t)(m + 8) * N + n) = o1;
        }
    }
}

// ---------------------------------------------------------------------------
// Flash attention with tf32 tensor cores — FA2 warp shape.
// CTA = (b, h, 128-row Q tile). 128 threads = 4 warps; warp w owns Q rows
// [w*32, w*32+32) as TWO m16 A-fragments -> every K/V B-fragment load is
// shared by 2 MMAs, halving the dominant smem B-traffic vs the 8-warp shape.
// Layouts and arithmetic identical to the proven R6 kernel (pitches 68/72,
// scalar fragment LDS, c-layout P round trip, fp32 softmax).
// ---------------------------------------------------------------------------
#define QT      128
#define KTILE   64
#define KP      68
#define VP      72
#define ATTN_SMEM_FLOATS (QT * KP + QT * KP + KTILE * KP + KTILE * VP)

__global__ __launch_bounds__(128, 2) void attn_mma_kernel(
    const float* __restrict__ Q, const float* __restrict__ K,
    const float* __restrict__ V, float* __restrict__ O)
{
    extern __shared__ float sm[];
    float* Qs = sm;                       // [128][KP]
    float* Ps = Qs + QT * KP;             // [128][KP]
    float* Ks = Ps + QT * KP;             // [64][KP]
    float* Vs = Ks + KTILE * KP;          // [64][VP]

    const int tid  = threadIdx.x;
    const int lane = tid & 31;
    const int warp = tid >> 5;    // 0..3
    const int r    = lane >> 2;   // fragment row group 0..7
    const int c    = lane & 3;    // fragment k/col group 0..3
    const int wq   = warp * 32;   // warp's 32-row Q strip

    const int q0 = blockIdx.x * QT;
    const int h  = blockIdx.y;
    const int b  = blockIdx.z;
    const size_t base = (size_t)b * SEQ * D_MODEL + (size_t)h * HEAD_DIM;

    // ---- load Q tile (128 x 64) -> Qs (tf32) ----
    #pragma unroll
    for (int i = 0; i < 16; i++) {
        const int idx  = i * 128 + tid;       // 2048 float4 slots
        const int row  = idx >> 4;            // 0..127
        const int col4 = (idx & 15) * 4;      // 0..60
        float4 v = *(const float4*)(Q + base + (size_t)(q0 + row) * D_MODEL + col4);
        Qs[row * KP + col4 + 0] = f2tf32(v.x);
        Qs[row * KP + col4 + 1] = f2tf32(v.y);
        Qs[row * KP + col4 + 2] = f2tf32(v.z);
        Qs[row * KP + col4 + 3] = f2tf32(v.w);
    }

    float oacc[2][8][4];
    float mv[2][2], lv[2][2];
    #pragma unroll
    for (int mi = 0; mi < 2; mi++) {
        mv[mi][0] = -1e30f; mv[mi][1] = -1e30f;
        lv[mi][0] = 0.f;    lv[mi][1] = 0.f;
        #pragma unroll
        for (int i = 0; i < 8; i++)
            #pragma unroll
            for (int j = 0; j < 4; j++) oacc[mi][i][j] = 0.f;
    }

    const float scale = 0.125f;   // 1/sqrt(64)

    for (int kt = 0; kt < SEQ / KTILE; kt++) {
        __syncthreads();   // previous iteration's consumers of Ks/Vs done

        // ---- load K,V tiles (64 x 64 each) -> smem (tf32) ----
        #pragma unroll
        for (int i = 0; i < 8; i++) {
            const int idx  = i * 128 + tid;       // 1024 float4 slots
            const int row  = idx >> 4;            // 0..63
            const int col4 = (idx & 15) * 4;
            const size_t g = base + (size_t)(kt * KTILE + row) * D_MODEL + col4;
            float4 kv = *(const float4*)(K + g);
            Ks[row * KP + col4 + 0] = f2tf32(kv.x);
            Ks[row * KP + col4 + 1] = f2tf32(kv.y);
            Ks[row * KP + col4 + 2] = f2tf32(kv.z);
            Ks[row * KP + col4 + 3] = f2tf32(kv.w);
            float4 vv = *(const float4*)(V + g);
            Vs[row * VP + col4 + 0] = f2tf32(vv.x);
            Vs[row * VP + col4 + 1] = f2tf32(vv.y);
            Vs[row * VP + col4 + 2] = f2tf32(vv.z);
            Vs[row * VP + col4 + 3] = f2tf32(vv.w);
        }
        __syncthreads();

        // ---- S = Q·K^T : 32 x 64 per warp; B frags shared by both m-frags ----
        float sacc[2][8][4];
        #pragma unroll
        for (int mi = 0; mi < 2; mi++)
            #pragma unroll
            for (int i = 0; i < 8; i++)
                #pragma unroll
                for (int j = 0; j < 4; j++) sacc[mi][i][j] = 0.f;

        #pragma unroll
        for (int kk = 0; kk < 8; kk++) {
            const int kb = kk * 8;
            float af[2][4];
            #pragma unroll
            for (int mi = 0; mi < 2; mi++) {
                const int rb = wq + mi * 16;
                af[mi][0] = Qs[(rb + r    ) * KP + kb + c    ];
                af[mi][1] = Qs[(rb + r + 8) * KP + kb + c    ];
                af[mi][2] = Qs[(rb + r    ) * KP + kb + c + 4];
                af[mi][3] = Qs[(rb + r + 8) * KP + kb + c + 4];
            }
            #pragma unroll
            for (int nt = 0; nt < 8; nt++) {
                float b0 = Ks[(nt * 8 + r) * KP + kb + c    ];
                float b1 = Ks[(nt * 8 + r) * KP + kb + c + 4];
                #pragma unroll
                for (int mi = 0; mi < 2; mi++)
                    mma_tf32(sacc[mi][nt][0], sacc[mi][nt][1], sacc[mi][nt][2], sacc[mi][nt][3],
                             af[mi][0], af[mi][1], af[mi][2], af[mi][3], b0, b1);
            }
        }

        // ---- online softmax per m-frag (rows r and r+8 within each) ----
        #pragma unroll
        for (int mi = 0; mi < 2; mi++) {
            float mx0 = -1e30f, mx1 = -1e30f;
            #pragma unroll
            for (int nt = 0; nt < 8; nt++) {
                sacc[mi][nt][0] *= scale; sacc[mi][nt][1] *= scale;
                sacc[mi][nt][2] *= scale; sacc[mi][nt][3] *= scale;
                mx0 = fmaxf(mx0, fmaxf(sacc[mi][nt][0], sacc[mi][nt][1]));
                mx1 = fmaxf(mx1, fmaxf(sacc[mi][nt][2], sacc[mi][nt][3]));
            }
            mx0 = fmaxf(mx0, __shfl_xor_sync(0xffffffffu, mx0, 1));
            mx0 = fmaxf(mx0, __shfl_xor_sync(0xffffffffu, mx0, 2));
            mx1 = fmaxf(mx1, __shfl_xor_sync(0xffffffffu, mx1, 1));
            mx1 = fmaxf(mx1, __shfl_xor_sync(0xffffffffu, mx1, 2));

            const float mn0 = fmaxf(mv[mi][0], mx0);
            const float mn1 = fmaxf(mv[mi][1], mx1);
            const float corr0 = __expf(mv[mi][0] - mn0);
            const float corr1 = __expf(mv[mi][1] - mn1);
            mv[mi][0] = mn0; mv[mi][1] = mn1;

            float rs0 = 0.f, rs1 = 0.f;
            #pragma unroll
            for (int nt = 0; nt < 8; nt++) {
                sacc[mi][nt][0] = __expf(sacc[mi][nt][0] - mn0);
                sacc[mi][nt][1] = __expf(sacc[mi][nt][1] - mn0);
                sacc[mi][nt][2] = __expf(sacc[mi][nt][2] - mn1);
                sacc[mi][nt][3] = __expf(sacc[mi][nt][3] - mn1);
                rs0 += sacc[mi][nt][0] + sacc[mi][nt][1];
                rs1 += sacc[mi][nt][2] + sacc[mi][nt][3];
            }
            rs0 += __shfl_xor_sync(0xffffffffu, rs0, 1);
            rs0 += __shfl_xor_sync(0xffffffffu, rs0, 2);
            rs1 += __shfl_xor_sync(0xffffffffu, rs1, 1);
            rs1 += __shfl_xor_sync(0xffffffffu, rs1, 2);

            lv[mi][0] = lv[mi][0] * corr0 + rs0;
            lv[mi][1] = lv[mi][1] * corr1 + rs1;
            #pragma unroll
            for (int nt = 0; nt < 8; nt++) {
                oacc[mi][nt][0] *= corr0; oacc[mi][nt][1] *= corr0;
                oacc[mi][nt][2] *= corr1; oacc[mi][nt][3] *= corr1;
            }

            // write P (accumulator layout) to warp-private smem rows
            const int rb = wq + mi * 16;
            #pragma unroll
            for (int nt = 0; nt < 8; nt++) {
                float2 p0 = make_float2(f2tf32(sacc[mi][nt][0]), f2tf32(sacc[mi][nt][1]));
                float2 p1 = make_float2(f2tf32(sacc[mi][nt][2]), f2tf32(sacc[mi][nt][3]));
                *(float2*)&Ps[(rb + r    ) * KP + nt * 8 + 2 * c] = p0;
                *(float2*)&Ps[(rb + r + 8) * KP + nt * 8 + 2 * c] = p1;
            }
        }
        __syncwarp();   // P rows warp-private

        // ---- O += P·V : B frags shared by both m-frags ----
        #pragma unroll
        for (int kk = 0; kk < 8; kk++) {
            const int kb = kk * 8;
            float af[2][4];
            #pragma unroll
            for (int mi = 0; mi < 2; mi++) {
                const int rb = wq + mi * 16;
                af[mi][0] = Ps[(rb + r    ) * KP + kb + c    ];
                af[mi][1] = Ps[(rb + r + 8) * KP + kb + c    ];
                af[mi][2] = Ps[(rb + r    ) * KP + kb + c + 4];
                af[mi][3] = Ps[(rb + r + 8) * KP + kb + c + 4];
            }
            #pragma unroll
            for (int nt = 0; nt < 8; nt++) {
                float b0 = Vs[(kb + c    ) * VP + nt * 8 + r];
                float b1 = Vs[(kb + c + 4) * VP + nt * 8 + r];
                #pragma unroll
                for (int mi = 0; mi < 2; mi++)
                    mma_tf32(oacc[mi][nt][0], oacc[mi][nt][1], oacc[mi][nt][2], oacc[mi][nt][3],
                             af[mi][0], af[mi][1], af[mi][2], af[mi][3], b0, b1);
            }
        }
    }

    // ---- normalize and write context ----
    #pragma unroll
    for (int mi = 0; mi < 2; mi++) {
        const float inv0 = 1.0f / lv[mi][0];
        const float inv1 = 1.0f / lv[mi][1];
        const int rb = wq + mi * 16;
        #pragma unroll
        for (int nt = 0; nt < 8; nt++) {
            const int col = nt * 8 + 2 * c;
            float2 o0 = make_float2(oacc[mi][nt][0] * inv0, oacc[mi][nt][1] * inv0);
            float2 o1 = make_float2(oacc[mi][nt][2] * inv1, oacc[mi][nt][3] * inv1);
            *(float2*)(O + base + (size_t)(q0 + rb + r    ) * D_MODEL + col) = o0;
            *(float2*)(O + base + (size_t)(q0 + rb + r + 8) * D_MODEL + col) = o1;
        }
    }
}

// ---------------------------------------------------------------------------
// Launch: Q/K/V projections -> attention -> output projection
// Inputs (metadata order): x1, x2, Wq, bq, Wk, bk, Wv, bv, Wo, bo
// ---------------------------------------------------------------------------
extern "C" void kernel_launch(void* const* d_in, const int* in_sizes, int n_in,
                              void* d_out, int out_size)
{
    (void)in_sizes; (void)n_in; (void)out_size;

    const float* x1 = (const float*)d_in[0];
    const float* x2 = (const float*)d_in[1];
    const float* Wq = (const float*)d_in[2];
    const float* bq = (const float*)d_in[3];
    const float* Wk = (const float*)d_in[4];
    const float* bk = (const float*)d_in[5];
    const float* Wv = (const float*)d_in[6];
    const float* bv = (const float*)d_in[7];
    const float* Wo = (const float*)d_in[8];
    const float* bo = (const float*)d_in[9];
    float* out = (float*)d_out;

    float *Qp, *Kp, *Vp, *Cp;
    cudaGetSymbolAddress((void**)&Qp, g_Q);
    cudaGetSymbolAddress((void**)&Kp, g_K);
    cudaGetSymbolAddress((void**)&Vp, g_V);
    cudaGetSymbolAddress((void**)&Cp, g_C);

    const int attn_smem = ATTN_SMEM_FLOATS * (int)sizeof(float);   // 105472 B
    cudaFuncSetAttribute(attn_mma_kernel,
                         cudaFuncAttributeMaxDynamicSharedMemorySize, attn_smem);

    dim3 gemm_grid(D_MODEL / 128, M_TOT / 128);   // (8, 32)

    gemm_tf32_kernel<<<gemm_grid, 256>>>(x1, Wq, bq, Qp, M_TOT, D_MODEL, D_MODEL);
    gemm_tf32_kernel<<<gemm_grid, 256>>>(x2, Wk, bk, Kp, M_TOT, D_MODEL, D_MODEL);
    gemm_tf32_kernel<<<gemm_grid, 256>>>(x2, Wv, bv, Vp, M_TOT, D_MODEL, D_MODEL);

    dim3 attn_grid(SEQ / QT, NUM_HEADS, B_SZ);    // (16, 16, 2)
    attn_mma_kernel<<<attn_grid, 128, attn_smem>>>(Qp, Kp, Vp, Cp);

    gemm_tf32_kernel<<<gemm_grid, 256>>>(Cp, Wo, bo, out, M_TOT, D_MODEL, D_MODEL);
}

// round 11
// speedup vs baseline: 1.3248x; 1.0559x over previous
#include <cuda_runtime.h>
#include <cstdint>
#include <cmath>

// Problem constants (fixed by the reference)
#define D_MODEL   1024
#define NUM_HEADS 16
#define HEAD_DIM  64
#define B_SZ      2
#define SEQ       2048
#define M_TOT     (B_SZ * SEQ)   // 4096 rows for all projection GEMMs

// Scratch (allocation-free rule: __device__ globals). 4 x 16 MB = 64 MB.
__device__ float g_Q[(size_t)M_TOT * D_MODEL];
__device__ float g_K[(size_t)M_TOT * D_MODEL];
__device__ float g_V[(size_t)M_TOT * D_MODEL];
__device__ float g_C[(size_t)M_TOT * D_MODEL];

// ---------------------------------------------------------------------------
// tf32 / cp.async helpers
// ---------------------------------------------------------------------------
__device__ __forceinline__ float f2tf32(float x) {
    asm("cvt.rna.tf32.f32 %0, %0;" : "+f"(x));
    return x;
}

__device__ __forceinline__ void mma_tf32(float& c0, float& c1, float& c2, float& c3,
                                         float a0, float a1, float a2, float a3,
                                         float b0, float b1)
{
    asm volatile(
        "mma.sync.aligned.m16n8k8.row.col.f32.tf32.tf32.f32 "
        "{%0,%1,%2,%3}, {%4,%5,%6,%7}, {%8,%9}, {%0,%1,%2,%3};\n"
        : "+f"(c0), "+f"(c1), "+f"(c2), "+f"(c3)
        : "r"(__float_as_uint(a0)), "r"(__float_as_uint(a1)),
          "r"(__float_as_uint(a2)), "r"(__float_as_uint(a3)),
          "r"(__float_as_uint(b0)), "r"(__float_as_uint(b1)));
}

__device__ __forceinline__ void cp_async16(uint32_t dst, const void* src) {
    asm volatile("cp.async.cg.shared.global [%0], [%1], 16;\n" :: "r"(dst), "l"(src));
}
#define CP_COMMIT() asm volatile("cp.async.commit_group;\n" ::: "memory")
#define CP_WAIT(n)  asm volatile("cp.async.wait_group %0;\n" :: "n"(n) : "memory")

// ---------------------------------------------------------------------------
// GEMM + bias (tf32 tensor cores, cp.async 4-stage pipeline)
//   Y[4096,1024] = X[4096,1024] @ W[1024,1024] + b
// CTA tile 128x128, BK=16, 256 threads = 8 warps (2m x 4n), warp tile 64x32.
// A kept in natural [m][k] layout, pitch 20 (20 mod 32 -> banks 20r+c,
// conflict-free for the A-fragment pattern, and 80-byte rows are 16B-aligned
// for cp.async). B in [k][n], pitch 132 (4 mod 32 -> banks 4c+r, conflict-free).
// tf32 rounding applied to fragments after LDS (FMA pipe is idle).
// ---------------------------------------------------------------------------
#define GEMM_M   4096
#define GEMM_N   1024
#define GEMM_K   1024
#define AP       20
#define BPITCH   132
#define A_STAGE  (128 * AP)     // 2560 floats
#define B_STAGE  (16 * BPITCH)  // 2112 floats
#define NSTAGE   4
#define GEMM_SMEM_FLOATS (NSTAGE * (A_STAGE + B_STAGE))   // 18688 -> 74752 B

__device__ __forceinline__ void gemm_issue_stage(
    uint32_t smem_u32, int s, int k0, int tid,
    const float* __restrict__ X, const float* __restrict__ W,
    int m0, int n0)
{
    // A: 128 rows x 16 k. Thread t loads 32 contiguous bytes:
    //    row = t>>1, k = k0 + 8*(t&1) + {0..7}
    {
        const int m  = tid >> 1;
        const int ko = 8 * (tid & 1);
        const float* src = X + (size_t)(m0 + m) * GEMM_K + k0 + ko;
        uint32_t dst = smem_u32 + (uint32_t)((s * A_STAGE + m * AP + ko) * 4);
        cp_async16(dst, src);
        cp_async16(dst + 16, src + 4);
    }
    // B: 16 k-rows x 128 n. Thread t loads rows t>>5 and t>>5+8, n chunk (t&31)*4
    {
        const int k  = tid >> 5;
        const int n4 = (tid & 31) * 4;
        const float* src = W + (size_t)(k0 + k) * GEMM_N + n0 + n4;
        uint32_t dst = smem_u32 +
            (uint32_t)((NSTAGE * A_STAGE + s * B_STAGE + k * BPITCH + n4) * 4);
        cp_async16(dst, src);
        cp_async16(dst + (uint32_t)(8 * BPITCH * 4), src + (size_t)8 * GEMM_N);
    }
}

__device__ __forceinline__ void gemm_body(
    const float* __restrict__ X, const float* __restrict__ W,
    const float* __restrict__ bias, float* __restrict__ Y)
{
    extern __shared__ __align__(16) float gsm[];
    uint32_t smem_u32 = (uint32_t)__cvta_generic_to_shared(gsm);

    const int tid  = threadIdx.x;
    const int lane = tid & 31;
    const int warp = tid >> 5;
    const int wm   = (warp >> 2) * 64;
    const int wn   = (warp & 3) * 32;
    const int r    = lane >> 2;
    const int c    = lane & 3;

    const int m0 = blockIdx.y * 128;
    const int n0 = blockIdx.x * 128;

    float acc[4][4][4];
    #pragma unroll
    for (int i = 0; i < 4; i++)
        #pragma unroll
        for (int j = 0; j < 4; j++)
            #pragma unroll
            for (int q = 0; q < 4; q++) acc[i][j][q] = 0.f;

    const int nIter = GEMM_K / 16;   // 64

    // prologue: stages 0..2 in flight
    #pragma unroll
    for (int s = 0; s < NSTAGE - 1; s++) {
        gemm_issue_stage(smem_u32, s, s * 16, tid, X, W, m0, n0);
        CP_COMMIT();
    }

    for (int it = 0; it < nIter; it++) {
        CP_WAIT(NSTAGE - 2);      // stage `it` landed
        __syncthreads();          // ...for every thread; prev buf fully consumed

        if (it + NSTAGE - 1 < nIter)
            gemm_issue_stage(smem_u32, (it + NSTAGE - 1) % NSTAGE,
                             (it + NSTAGE - 1) * 16, tid, X, W, m0, n0);
        CP_COMMIT();              // one group per iteration (may be empty)

        const int buf = it % NSTAGE;
        const float* Ab = gsm + buf * A_STAGE;
        const float* Bb = gsm + NSTAGE * A_STAGE + buf * B_STAGE;

        #pragma unroll
        for (int s = 0; s < 2; s++) {
            const int kb = s * 8;
            float af[4][4], bf[4][2];
            #pragma unroll
            for (int mi = 0; mi < 4; mi++) {
                const int mb = wm + 16 * mi;
                af[mi][0] = f2tf32(Ab[(mb + r    ) * AP + kb + c    ]);
                af[mi][1] = f2tf32(Ab[(mb + r + 8) * AP + kb + c    ]);
                af[mi][2] = f2tf32(Ab[(mb + r    ) * AP + kb + c + 4]);
                af[mi][3] = f2tf32(Ab[(mb + r + 8) * AP + kb + c + 4]);
            }
            #pragma unroll
            for (int ni = 0; ni < 4; ni++) {
                const int nb = wn + 8 * ni;
                bf[ni][0] = f2tf32(Bb[(kb + c    ) * BPITCH + nb + r]);
                bf[ni][1] = f2tf32(Bb[(kb + c + 4) * BPITCH + nb + r]);
            }
            #pragma unroll
            for (int mi = 0; mi < 4; mi++)
                #pragma unroll
                for (int ni = 0; ni < 4; ni++)
                    mma_tf32(acc[mi][ni][0], acc[mi][ni][1], acc[mi][ni][2], acc[mi][ni][3],
                             af[mi][0], af[mi][1], af[mi][2], af[mi][3],
                             bf[ni][0], bf[ni][1]);
        }
    }

    // epilogue: add bias, write. c-frag layout: rows r, r+8; cols 2c, 2c+1.
    #pragma unroll
    for (int mi = 0; mi < 4; mi++) {
        const int m = m0 + wm + 16 * mi + r;
        #pragma unroll
        for (int ni = 0; ni < 4; ni++) {
            const int n = n0 + wn + 8 * ni + 2 * c;
            const float bx = bias[n], by = bias[n + 1];
            float2 o0 = make_float2(acc[mi][ni][0] + bx, acc[mi][ni][1] + by);
            float2 o1 = make_float2(acc[mi][ni][2] + bx, acc[mi][ni][3] + by);
            *(float2*)(Y + (size_t)m * GEMM_N + n)       = o0;
            *(float2*)(Y + (size_t)(m + 8) * GEMM_N + n) = o1;
        }
    }
}

// Merged Q/K/V projection: blockIdx.z selects which projection this CTA does.
__global__ __launch_bounds__(256, 2) void qkv_gemm_kernel(
    const float* __restrict__ x1, const float* __restrict__ x2,
    const float* __restrict__ Wq, const float* __restrict__ bq,
    const float* __restrict__ Wk, const float* __restrict__ bk,
    const float* __restrict__ Wv, const float* __restrict__ bv,
    float* __restrict__ Qp, float* __restrict__ Kp, float* __restrict__ Vp)
{
    const float *X, *W, *bias;
    float* Y;
    if (blockIdx.z == 0)      { X = x1; W = Wq; bias = bq; Y = Qp; }
    else if (blockIdx.z == 1) { X = x2; W = Wk; bias = bk; Y = Kp; }
    else                      { X = x2; W = Wv; bias = bv; Y = Vp; }
    gemm_body(X, W, bias, Y);
}

__global__ __launch_bounds__(256, 2) void out_gemm_kernel(
    const float* __restrict__ X, const float* __restrict__ W,
    const float* __restrict__ bias, float* __restrict__ Y)
{
    gemm_body(X, W, bias, Y);
}

// ---------------------------------------------------------------------------
// Flash attention with tf32 tensor cores — FA2 warp shape (proven, R8).
// CTA = (b, h, 128-row Q tile). 128 threads = 4 warps; warp w owns Q rows
// [w*32, w*32+32) as TWO m16 A-fragments.
// ---------------------------------------------------------------------------
#define QT      128
#define KTILE   64
#define KP      68
#define VP      72
#define ATTN_SMEM_FLOATS (QT * KP + QT * KP + KTILE * KP + KTILE * VP)

__global__ __launch_bounds__(128, 2) void attn_mma_kernel(
    const float* __restrict__ Q, const float* __restrict__ K,
    const float* __restrict__ V, float* __restrict__ O)
{
    extern __shared__ float sm[];
    float* Qs = sm;                       // [128][KP]
    float* Ps = Qs + QT * KP;             // [128][KP]
    float* Ks = Ps + QT * KP;             // [64][KP]
    float* Vs = Ks + KTILE * KP;          // [64][VP]

    const int tid  = threadIdx.x;
    const int lane = tid & 31;
    const int warp = tid >> 5;    // 0..3
    const int r    = lane >> 2;   // fragment row group 0..7
    const int c    = lane & 3;    // fragment k/col group 0..3
    const int wq   = warp * 32;   // warp's 32-row Q strip

    const int q0 = blockIdx.x * QT;
    const int h  = blockIdx.y;
    const int b  = blockIdx.z;
    const size_t base = (size_t)b * SEQ * D_MODEL + (size_t)h * HEAD_DIM;

    // ---- load Q tile (128 x 64) -> Qs (tf32) ----
    #pragma unroll
    for (int i = 0; i < 16; i++) {
        const int idx  = i * 128 + tid;       // 2048 float4 slots
        const int row  = idx >> 4;            // 0..127
        const int col4 = (idx & 15) * 4;      // 0..60
        float4 v = *(const float4*)(Q + base + (size_t)(q0 + row) * D_MODEL + col4);
        Qs[row * KP + col4 + 0] = f2tf32(v.x);
        Qs[row * KP + col4 + 1] = f2tf32(v.y);
        Qs[row * KP + col4 + 2] = f2tf32(v.z);
        Qs[row * KP + col4 + 3] = f2tf32(v.w);
    }

    float oacc[2][8][4];
    float mv[2][2], lv[2][2];
    #pragma unroll
    for (int mi = 0; mi < 2; mi++) {
        mv[mi][0] = -1e30f; mv[mi][1] = -1e30f;
        lv[mi][0] = 0.f;    lv[mi][1] = 0.f;
        #pragma unroll
        for (int i = 0; i < 8; i++)
            #pragma unroll
            for (int j = 0; j < 4; j++) oacc[mi][i][j] = 0.f;
    }

    const float scale = 0.125f;   // 1/sqrt(64)

    for (int kt = 0; kt < SEQ / KTILE; kt++) {
        __syncthreads();   // previous iteration's consumers of Ks/Vs done

        // ---- load K,V tiles (64 x 64 each) -> smem (tf32) ----
        #pragma unroll
        for (int i = 0; i < 8; i++) {
            const int idx  = i * 128 + tid;       // 1024 float4 slots
            const int row  = idx >> 4;            // 0..63
            const int col4 = (idx & 15) * 4;
            const size_t g = base + (size_t)(kt * KTILE + row) * D_MODEL + col4;
            float4 kv = *(const float4*)(K + g);
            Ks[row * KP + col4 + 0] = f2tf32(kv.x);
            Ks[row * KP + col4 + 1] = f2tf32(kv.y);
            Ks[row * KP + col4 + 2] = f2tf32(kv.z);
            Ks[row * KP + col4 + 3] = f2tf32(kv.w);
            float4 vv = *(const float4*)(V + g);
            Vs[row * VP + col4 + 0] = f2tf32(vv.x);
            Vs[row * VP + col4 + 1] = f2tf32(vv.y);
            Vs[row * VP + col4 + 2] = f2tf32(vv.z);
            Vs[row * VP + col4 + 3] = f2tf32(vv.w);
        }
        __syncthreads();

        // ---- S = Q·K^T : 32 x 64 per warp; B frags shared by both m-frags ----
        float sacc[2][8][4];
        #pragma unroll
        for (int mi = 0; mi < 2; mi++)
            #pragma unroll
            for (int i = 0; i < 8; i++)
                #pragma unroll
                for (int j = 0; j < 4; j++) sacc[mi][i][j] = 0.f;

        #pragma unroll
        for (int kk = 0; kk < 8; kk++) {
            const int kb = kk * 8;
            float af[2][4];
            #pragma unroll
            for (int mi = 0; mi < 2; mi++) {
                const int rb = wq + mi * 16;
                af[mi][0] = Qs[(rb + r    ) * KP + kb + c    ];
                af[mi][1] = Qs[(rb + r + 8) * KP + kb + c    ];
                af[mi][2] = Qs[(rb + r    ) * KP + kb + c + 4];
                af[mi][3] = Qs[(rb + r + 8) * KP + kb + c + 4];
            }
            #pragma unroll
            for (int nt = 0; nt < 8; nt++) {
                float b0 = Ks[(nt * 8 + r) * KP + kb + c    ];
                float b1 = Ks[(nt * 8 + r) * KP + kb + c + 4];
                #pragma unroll
                for (int mi = 0; mi < 2; mi++)
                    mma_tf32(sacc[mi][nt][0], sacc[mi][nt][1], sacc[mi][nt][2], sacc[mi][nt][3],
                             af[mi][0], af[mi][1], af[mi][2], af[mi][3], b0, b1);
            }
        }

        // ---- online softmax per m-frag (rows r and r+8 within each) ----
        #pragma unroll
        for (int mi = 0; mi < 2; mi++) {
            float mx0 = -1e30f, mx1 = -1e30f;
            #pragma unroll
            for (int nt = 0; nt < 8; nt++) {
                sacc[mi][nt][0] *= scale; sacc[mi][nt][1] *= scale;
                sacc[mi][nt][2] *= scale; sacc[mi][nt][3] *= scale;
                mx0 = fmaxf(mx0, fmaxf(sacc[mi][nt][0], sacc[mi][nt][1]));
                mx1 = fmaxf(mx1, fmaxf(sacc[mi][nt][2], sacc[mi][nt][3]));
            }
            mx0 = fmaxf(mx0, __shfl_xor_sync(0xffffffffu, mx0, 1));
            mx0 = fmaxf(mx0, __shfl_xor_sync(0xffffffffu, mx0, 2));
            mx1 = fmaxf(mx1, __shfl_xor_sync(0xffffffffu, mx1, 1));
            mx1 = fmaxf(mx1, __shfl_xor_sync(0xffffffffu, mx1, 2));

            const float mn0 = fmaxf(mv[mi][0], mx0);
            const float mn1 = fmaxf(mv[mi][1], mx1);
            const float corr0 = __expf(mv[mi][0] - mn0);
            const float corr1 = __expf(mv[mi][1] - mn1);
            mv[mi][0] = mn0; mv[mi][1] = mn1;

            float rs0 = 0.f, rs1 = 0.f;
            #pragma unroll
            for (int nt = 0; nt < 8; nt++) {
                sacc[mi][nt][0] = __expf(sacc[mi][nt][0] - mn0);
                sacc[mi][nt][1] = __expf(sacc[mi][nt][1] - mn0);
                sacc[mi][nt][2] = __expf(sacc[mi][nt][2] - mn1);
                sacc[mi][nt][3] = __expf(sacc[mi][nt][3] - mn1);
                rs0 += sacc[mi][nt][0] + sacc[mi][nt][1];
                rs1 += sacc[mi][nt][2] + sacc[mi][nt][3];
            }
            rs0 += __shfl_xor_sync(0xffffffffu, rs0, 1);
            rs0 += __shfl_xor_sync(0xffffffffu, rs0, 2);
            rs1 += __shfl_xor_sync(0xffffffffu, rs1, 1);
            rs1 += __shfl_xor_sync(0xffffffffu, rs1, 2);

            lv[mi][0] = lv[mi][0] * corr0 + rs0;
            lv[mi][1] = lv[mi][1] * corr1 + rs1;
            #pragma unroll
            for (int nt = 0; nt < 8; nt++) {
                oacc[mi][nt][0] *= corr0; oacc[mi][nt][1] *= corr0;
                oacc[mi][nt][2] *= corr1; oacc[mi][nt][3] *= corr1;
            }

            // write P (accumulator layout) to warp-private smem rows
            const int rb = wq + mi * 16;
            #pragma unroll
            for (int nt = 0; nt < 8; nt++) {
                float2 p0 = make_float2(f2tf32(sacc[mi][nt][0]), f2tf32(sacc[mi][nt][1]));
                float2 p1 = make_float2(f2tf32(sacc[mi][nt][2]), f2tf32(sacc[mi][nt][3]));
                *(float2*)&Ps[(rb + r    ) * KP + nt * 8 + 2 * c] = p0;
                *(float2*)&Ps[(rb + r + 8) * KP + nt * 8 + 2 * c] = p1;
            }
        }
        __syncwarp();   // P rows warp-private

        // ---- O += P·V : B frags shared by both m-frags ----
        #pragma unroll
        for (int kk = 0; kk < 8; kk++) {
            const int kb = kk * 8;
            float af[2][4];
            #pragma unroll
            for (int mi = 0; mi < 2; mi++) {
                const int rb = wq + mi * 16;
                af[mi][0] = Ps[(rb + r    ) * KP + kb + c    ];
                af[mi][1] = Ps[(rb + r + 8) * KP + kb + c    ];
                af[mi][2] = Ps[(rb + r    ) * KP + kb + c + 4];
                af[mi][3] = Ps[(rb + r + 8) * KP + kb + c + 4];
            }
            #pragma unroll
            for (int nt = 0; nt < 8; nt++) {
                float b0 = Vs[(kb + c    ) * VP + nt * 8 + r];
                float b1 = Vs[(kb + c + 4) * VP + nt * 8 + r];
                #pragma unroll
                for (int mi = 0; mi < 2; mi++)
                    mma_tf32(oacc[mi][nt][0], oacc[mi][nt][1], oacc[mi][nt][2], oacc[mi][nt][3],
                             af[mi][0], af[mi][1], af[mi][2], af[mi][3], b0, b1);
            }
        }
    }

    // ---- normalize and write context ----
    #pragma unroll
    for (int mi = 0; mi < 2; mi++) {
        const float inv0 = 1.0f / lv[mi][0];
        const float inv1 = 1.0f / lv[mi][1];
        const int rb = wq + mi * 16;
        #pragma unroll
        for (int nt = 0; nt < 8; nt++) {
            const int col = nt * 8 + 2 * c;
            float2 o0 = make_float2(oacc[mi][nt][0] * inv0, oacc[mi][nt][1] * inv0);
            float2 o1 = make_float2(oacc[mi][nt][2] * inv1, oacc[mi][nt][3] * inv1);
            *(float2*)(O + base + (size_t)(q0 + rb + r    ) * D_MODEL + col) = o0;
            *(float2*)(O + base + (size_t)(q0 + rb + r + 8) * D_MODEL + col) = o1;
        }
    }
}

// ---------------------------------------------------------------------------
// Launch: merged QKV projection -> attention -> output projection
// Inputs (metadata order): x1, x2, Wq, bq, Wk, bk, Wv, bv, Wo, bo
// ---------------------------------------------------------------------------
extern "C" void kernel_launch(void* const* d_in, const int* in_sizes, int n_in,
                              void* d_out, int out_size)
{
    (void)in_sizes; (void)n_in; (void)out_size;

    const float* x1 = (const float*)d_in[0];
    const float* x2 = (const float*)d_in[1];
    const float* Wq = (const float*)d_in[2];
    const float* bq = (const float*)d_in[3];
    const float* Wk = (const float*)d_in[4];
    const float* bk = (const float*)d_in[5];
    const float* Wv = (const float*)d_in[6];
    const float* bv = (const float*)d_in[7];
    const float* Wo = (const float*)d_in[8];
    const float* bo = (const float*)d_in[9];
    float* out = (float*)d_out;

    float *Qp, *Kp, *Vp, *Cp;
    cudaGetSymbolAddress((void**)&Qp, g_Q);
    cudaGetSymbolAddress((void**)&Kp, g_K);
    cudaGetSymbolAddress((void**)&Vp, g_V);
    cudaGetSymbolAddress((void**)&Cp, g_C);

    const int gemm_smem = GEMM_SMEM_FLOATS * (int)sizeof(float);   // 74752 B
    cudaFuncSetAttribute(qkv_gemm_kernel,
                         cudaFuncAttributeMaxDynamicSharedMemorySize, gemm_smem);
    cudaFuncSetAttribute(out_gemm_kernel,
                         cudaFuncAttributeMaxDynamicSharedMemorySize, gemm_smem);

    const int attn_smem = ATTN_SMEM_FLOATS * (int)sizeof(float);   // 105472 B
    cudaFuncSetAttribute(attn_mma_kernel,
                         cudaFuncAttributeMaxDynamicSharedMemorySize, attn_smem);

    dim3 qkv_grid(GEMM_N / 128, GEMM_M / 128, 3);   // (8, 32, 3)
    qkv_gemm_kernel<<<qkv_grid, 256, gemm_smem>>>(x1, x2, Wq, bq, Wk, bk, Wv, bv,
                                                  Qp, Kp, Vp);

    dim3 attn_grid(SEQ / QT, NUM_HEADS, B_SZ);      // (16, 16, 2)
    attn_mma_kernel<<<attn_grid, 128, attn_smem>>>(Qp, Kp, Vp, Cp);

    dim3 out_grid(GEMM_N / 128, GEMM_M / 128);      // (8, 32)
    out_gemm_kernel<<<out_grid, 256, gemm_smem>>>(Cp, Wo, bo, out);
}

// round 12
// speedup vs baseline: 1.3782x; 1.0403x over previous
#include <cuda_runtime.h>
#include <cstdint>
#include <cmath>

// Problem constants (fixed by the reference)
#define D_MODEL   1024
#define NUM_HEADS 16
#define HEAD_DIM  64
#define B_SZ      2
#define SEQ       2048
#define M_TOT     (B_SZ * SEQ)   // 4096 rows for all projection GEMMs

// Scratch (allocation-free rule: __device__ globals). 4 x 16 MB = 64 MB.
__device__ float g_Q[(size_t)M_TOT * D_MODEL];
__device__ float g_K[(size_t)M_TOT * D_MODEL];
__device__ float g_V[(size_t)M_TOT * D_MODEL];
__device__ float g_C[(size_t)M_TOT * D_MODEL];

// ---------------------------------------------------------------------------
// tf32 / cp.async helpers
// ---------------------------------------------------------------------------
__device__ __forceinline__ float f2tf32(float x) {
    asm("cvt.rna.tf32.f32 %0, %0;" : "+f"(x));
    return x;
}

__device__ __forceinline__ void mma_tf32(float& c0, float& c1, float& c2, float& c3,
                                         float a0, float a1, float a2, float a3,
                                         float b0, float b1)
{
    asm volatile(
        "mma.sync.aligned.m16n8k8.row.col.f32.tf32.tf32.f32 "
        "{%0,%1,%2,%3}, {%4,%5,%6,%7}, {%8,%9}, {%0,%1,%2,%3};\n"
        : "+f"(c0), "+f"(c1), "+f"(c2), "+f"(c3)
        : "r"(__float_as_uint(a0)), "r"(__float_as_uint(a1)),
          "r"(__float_as_uint(a2)), "r"(__float_as_uint(a3)),
          "r"(__float_as_uint(b0)), "r"(__float_as_uint(b1)));
}

__device__ __forceinline__ void cp_async16(uint32_t dst, const void* src) {
    asm volatile("cp.async.cg.shared.global [%0], [%1], 16;\n" :: "r"(dst), "l"(src));
}
#define CP_COMMIT() asm volatile("cp.async.commit_group;\n" ::: "memory")
#define CP_WAIT(n)  asm volatile("cp.async.wait_group %0;\n" :: "n"(n) : "memory")

// ---------------------------------------------------------------------------
// GEMM + bias (tf32 tensor cores, cp.async 4-stage pipeline)
//   Y[4096,1024] = X[4096,1024] @ W[1024,1024] + b
// CTA tile 128x128, BK=16, 128 threads = 4 warps (2m x 2n), warp tile 64x64.
// The fat warp tile amortizes fragment loads: per thread per iteration
// 32 A-LDS + 32 B-LDS feed 64 MMAs (1:1 aux:MMA, was 3:1 with 8 warps).
// A in natural [m][k], pitch 20 (banks 20r+c — conflict-free).
// B in [k][n], pitch 132 (banks 4c+r — conflict-free).
// tf32 rounding applied to fragments after LDS (FMA pipe nearly idle).
// ---------------------------------------------------------------------------
#define GEMM_M   4096
#define GEMM_N   1024
#define GEMM_K   1024
#define AP       20
#define BPITCH   132
#define A_STAGE  (128 * AP)     // 2560 floats
#define B_STAGE  (16 * BPITCH)  // 2112 floats
#define NSTAGE   4
#define GEMM_SMEM_FLOATS (NSTAGE * (A_STAGE + B_STAGE))   // 18688 -> 74752 B

__device__ __forceinline__ void gemm_issue_stage(
    uint32_t smem_u32, int s, int k0, int tid,
    const float* __restrict__ X, const float* __restrict__ W,
    int m0, int n0)
{
    // A: 128 rows x 16 k = 512 float4 slots; 4 per thread.
    #pragma unroll
    for (int i = 0; i < 4; i++) {
        const int idx = i * 128 + tid;        // 0..511
        const int m   = idx >> 2;             // 0..127
        const int ko  = (idx & 3) * 4;        // 0,4,8,12
        const float* src = X + (size_t)(m0 + m) * GEMM_K + k0 + ko;
        uint32_t dst = smem_u32 + (uint32_t)((s * A_STAGE + m * AP + ko) * 4);
        cp_async16(dst, src);
    }
    // B: 16 k-rows x 128 n = 512 float4 slots; 4 per thread.
    #pragma unroll
    for (int i = 0; i < 4; i++) {
        const int idx = i * 128 + tid;        // 0..511
        const int k   = idx >> 5;             // 0..15
        const int n4  = (idx & 31) * 4;       // 0..124
        const float* src = W + (size_t)(k0 + k) * GEMM_N + n0 + n4;
        uint32_t dst = smem_u32 +
            (uint32_t)((NSTAGE * A_STAGE + s * B_STAGE + k * BPITCH + n4) * 4);
        cp_async16(dst, src);
    }
}

__device__ __forceinline__ void gemm_body(
    const float* __restrict__ X, const float* __restrict__ W,
    const float* __restrict__ bias, float* __restrict__ Y)
{
    extern __shared__ __align__(16) float gsm[];
    uint32_t smem_u32 = (uint32_t)__cvta_generic_to_shared(gsm);

    const int tid  = threadIdx.x;
    const int lane = tid & 31;
    const int warp = tid >> 5;           // 0..3
    const int wm   = (warp >> 1) * 64;   // warp m offset
    const int wn   = (warp & 1) * 64;    // warp n offset
    const int r    = lane >> 2;
    const int c    = lane & 3;

    const int m0 = blockIdx.y * 128;
    const int n0 = blockIdx.x * 128;

    float acc[4][8][4];
    #pragma unroll
    for (int i = 0; i < 4; i++)
        #pragma unroll
        for (int j = 0; j < 8; j++)
            #pragma unroll
            for (int q = 0; q < 4; q++) acc[i][j][q] = 0.f;

    const int nIter = GEMM_K / 16;   // 64

    // prologue: stages 0..2 in flight
    #pragma unroll
    for (int s = 0; s < NSTAGE - 1; s++) {
        gemm_issue_stage(smem_u32, s, s * 16, tid, X, W, m0, n0);
        CP_COMMIT();
    }

    for (int it = 0; it < nIter; it++) {
        CP_WAIT(NSTAGE - 2);      // stage `it` landed
        __syncthreads();          // ...for every thread; prev buf fully consumed

        if (it + NSTAGE - 1 < nIter)
            gemm_issue_stage(smem_u32, (it + NSTAGE - 1) % NSTAGE,
                             (it + NSTAGE - 1) * 16, tid, X, W, m0, n0);
        CP_COMMIT();              // one group per iteration (may be empty)

        const int buf = it % NSTAGE;
        const float* Ab = gsm + buf * A_STAGE;
        const float* Bb = gsm + NSTAGE * A_STAGE + buf * B_STAGE;

        #pragma unroll
        for (int s = 0; s < 2; s++) {
            const int kb = s * 8;
            float af[4][4], bf[8][2];
            #pragma unroll
            for (int mi = 0; mi < 4; mi++) {
                const int mb = wm + 16 * mi;
                af[mi][0] = f2tf32(Ab[(mb + r    ) * AP + kb + c    ]);
                af[mi][1] = f2tf32(Ab[(mb + r + 8) * AP + kb + c    ]);
                af[mi][2] = f2tf32(Ab[(mb + r    ) * AP + kb + c + 4]);
                af[mi][3] = f2tf32(Ab[(mb + r + 8) * AP + kb + c + 4]);
            }
            #pragma unroll
            for (int ni = 0; ni < 8; ni++) {
                const int nb = wn + 8 * ni;
                bf[ni][0] = f2tf32(Bb[(kb + c    ) * BPITCH + nb + r]);
                bf[ni][1] = f2tf32(Bb[(kb + c + 4) * BPITCH + nb + r]);
            }
            #pragma unroll
            for (int mi = 0; mi < 4; mi++)
                #pragma unroll
                for (int ni = 0; ni < 8; ni++)
                    mma_tf32(acc[mi][ni][0], acc[mi][ni][1], acc[mi][ni][2], acc[mi][ni][3],
                             af[mi][0], af[mi][1], af[mi][2], af[mi][3],
                             bf[ni][0], bf[ni][1]);
        }
    }

    // epilogue: add bias, write. c-frag layout: rows r, r+8; cols 2c, 2c+1.
    #pragma unroll
    for (int mi = 0; mi < 4; mi++) {
        const int m = m0 + wm + 16 * mi + r;
        #pragma unroll
        for (int ni = 0; ni < 8; ni++) {
            const int n = n0 + wn + 8 * ni + 2 * c;
            const float bx = bias[n], by = bias[n + 1];
            float2 o0 = make_float2(acc[mi][ni][0] + bx, acc[mi][ni][1] + by);
            float2 o1 = make_float2(acc[mi][ni][2] + bx, acc[mi][ni][3] + by);
            *(float2*)(Y + (size_t)m * GEMM_N + n)       = o0;
            *(float2*)(Y + (size_t)(m + 8) * GEMM_N + n) = o1;
        }
    }
}

// Merged Q/K/V projection: blockIdx.z selects which projection this CTA does.
__global__ __launch_bounds__(128, 2) void qkv_gemm_kernel(
    const float* __restrict__ x1, const float* __restrict__ x2,
    const float* __restrict__ Wq, const float* __restrict__ bq,
    const float* __restrict__ Wk, const float* __restrict__ bk,
    const float* __restrict__ Wv, const float* __restrict__ bv,
    float* __restrict__ Qp, float* __restrict__ Kp, float* __restrict__ Vp)
{
    const float *X, *W, *bias;
    float* Y;
    if (blockIdx.z == 0)      { X = x1; W = Wq; bias = bq; Y = Qp; }
    else if (blockIdx.z == 1) { X = x2; W = Wk; bias = bk; Y = Kp; }
    else                      { X = x2; W = Wv; bias = bv; Y = Vp; }
    gemm_body(X, W, bias, Y);
}

__global__ __launch_bounds__(128, 2) void out_gemm_kernel(
    const float* __restrict__ X, const float* __restrict__ W,
    const float* __restrict__ bias, float* __restrict__ Y)
{
    gemm_body(X, W, bias, Y);
}

// ---------------------------------------------------------------------------
// Flash attention with tf32 tensor cores — FA2 warp shape (proven, R8).
// CTA = (b, h, 128-row Q tile). 128 threads = 4 warps; warp w owns Q rows
// [w*32, w*32+32) as TWO m16 A-fragments.
// ---------------------------------------------------------------------------
#define QT      128
#define KTILE   64
#define KP      68
#define VP      72
#define ATTN_SMEM_FLOATS (QT * KP + QT * KP + KTILE * KP + KTILE * VP)

__global__ __launch_bounds__(128, 2) void attn_mma_kernel(
    const float* __restrict__ Q, const float* __restrict__ K,
    const float* __restrict__ V, float* __restrict__ O)
{
    extern __shared__ float sm[];
    float* Qs = sm;                       // [128][KP]
    float* Ps = Qs + QT * KP;             // [128][KP]
    float* Ks = Ps + QT * KP;             // [64][KP]
    float* Vs = Ks + KTILE * KP;          // [64][VP]

    const int tid  = threadIdx.x;
    const int lane = tid & 31;
    const int warp = tid >> 5;    // 0..3
    const int r    = lane >> 2;   // fragment row group 0..7
    const int c    = lane & 3;    // fragment k/col group 0..3
    const int wq   = warp * 32;   // warp's 32-row Q strip

    const int q0 = blockIdx.x * QT;
    const int h  = blockIdx.y;
    const int b  = blockIdx.z;
    const size_t base = (size_t)b * SEQ * D_MODEL + (size_t)h * HEAD_DIM;

    // ---- load Q tile (128 x 64) -> Qs (tf32) ----
    #pragma unroll
    for (int i = 0; i < 16; i++) {
        const int idx  = i * 128 + tid;       // 2048 float4 slots
        const int row  = idx >> 4;            // 0..127
        const int col4 = (idx & 15) * 4;      // 0..60
        float4 v = *(const float4*)(Q + base + (size_t)(q0 + row) * D_MODEL + col4);
        Qs[row * KP + col4 + 0] = f2tf32(v.x);
        Qs[row * KP + col4 + 1] = f2tf32(v.y);
        Qs[row * KP + col4 + 2] = f2tf32(v.z);
        Qs[row * KP + col4 + 3] = f2tf32(v.w);
    }

    float oacc[2][8][4];
    float mv[2][2], lv[2][2];
    #pragma unroll
    for (int mi = 0; mi < 2; mi++) {
        mv[mi][0] = -1e30f; mv[mi][1] = -1e30f;
        lv[mi][0] = 0.f;    lv[mi][1] = 0.f;
        #pragma unroll
        for (int i = 0; i < 8; i++)
            #pragma unroll
            for (int j = 0; j < 4; j++) oacc[mi][i][j] = 0.f;
    }

    const float scale = 0.125f;   // 1/sqrt(64)

    for (int kt = 0; kt < SEQ / KTILE; kt++) {
        __syncthreads();   // previous iteration's consumers of Ks/Vs done

        // ---- load K,V tiles (64 x 64 each) -> smem (tf32) ----
        #pragma unroll
        for (int i = 0; i < 8; i++) {
            const int idx  = i * 128 + tid;       // 1024 float4 slots
            const int row  = idx >> 4;            // 0..63
            const int col4 = (idx & 15) * 4;
            const size_t g = base + (size_t)(kt * KTILE + row) * D_MODEL + col4;
            float4 kv = *(const float4*)(K + g);
            Ks[row * KP + col4 + 0] = f2tf32(kv.x);
            Ks[row * KP + col4 + 1] = f2tf32(kv.y);
            Ks[row * KP + col4 + 2] = f2tf32(kv.z);
            Ks[row * KP + col4 + 3] = f2tf32(kv.w);
            float4 vv = *(const float4*)(V + g);
            Vs[row * VP + col4 + 0] = f2tf32(vv.x);
            Vs[row * VP + col4 + 1] = f2tf32(vv.y);
            Vs[row * VP + col4 + 2] = f2tf32(vv.z);
            Vs[row * VP + col4 + 3] = f2tf32(vv.w);
        }
        __syncthreads();

        // ---- S = Q·K^T : 32 x 64 per warp; B frags shared by both m-frags ----
        float sacc[2][8][4];
        #pragma unroll
        for (int mi = 0; mi < 2; mi++)
            #pragma unroll
            for (int i = 0; i < 8; i++)
                #pragma unroll
                for (int j = 0; j < 4; j++) sacc[mi][i][j] = 0.f;

        #pragma unroll
        for (int kk = 0; kk < 8; kk++) {
            const int kb = kk * 8;
            float af[2][4];
            #pragma unroll
            for (int mi = 0; mi < 2; mi++) {
                const int rb = wq + mi * 16;
                af[mi][0] = Qs[(rb + r    ) * KP + kb + c    ];
                af[mi][1] = Qs[(rb + r + 8) * KP + kb + c    ];
                af[mi][2] = Qs[(rb + r    ) * KP + kb + c + 4];
                af[mi][3] = Qs[(rb + r + 8) * KP + kb + c + 4];
            }
            #pragma unroll
            for (int nt = 0; nt < 8; nt++) {
                float b0 = Ks[(nt * 8 + r) * KP + kb + c    ];
                float b1 = Ks[(nt * 8 + r) * KP + kb + c + 4];
                #pragma unroll
                for (int mi = 0; mi < 2; mi++)
                    mma_tf32(sacc[mi][nt][0], sacc[mi][nt][1], sacc[mi][nt][2], sacc[mi][nt][3],
                             af[mi][0], af[mi][1], af[mi][2], af[mi][3], b0, b1);
            }
        }

        // ---- online softmax per m-frag (rows r and r+8 within each) ----
        #pragma unroll
        for (int mi = 0; mi < 2; mi++) {
            float mx0 = -1e30f, mx1 = -1e30f;
            #pragma unroll
            for (int nt = 0; nt < 8; nt++) {
                sacc[mi][nt][0] *= scale; sacc[mi][nt][1] *= scale;
                sacc[mi][nt][2] *= scale; sacc[mi][nt][3] *= scale;
                mx0 = fmaxf(mx0, fmaxf(sacc[mi][nt][0], sacc[mi][nt][1]));
                mx1 = fmaxf(mx1, fmaxf(sacc[mi][nt][2], sacc[mi][nt][3]));
            }
            mx0 = fmaxf(mx0, __shfl_xor_sync(0xffffffffu, mx0, 1));
            mx0 = fmaxf(mx0, __shfl_xor_sync(0xffffffffu, mx0, 2));
            mx1 = fmaxf(mx1, __shfl_xor_sync(0xffffffffu, mx1, 1));
            mx1 = fmaxf(mx1, __shfl_xor_sync(0xffffffffu, mx1, 2));

            const float mn0 = fmaxf(mv[mi][0], mx0);
            const float mn1 = fmaxf(mv[mi][1], mx1);
            const float corr0 = __expf(mv[mi][0] - mn0);
            const float corr1 = __expf(mv[mi][1] - mn1);
            mv[mi][0] = mn0; mv[mi][1] = mn1;

            float rs0 = 0.f, rs1 = 0.f;
            #pragma unroll
            for (int nt = 0; nt < 8; nt++) {
                sacc[mi][nt][0] = __expf(sacc[mi][nt][0] - mn0);
                sacc[mi][nt][1] = __expf(sacc[mi][nt][1] - mn0);
                sacc[mi][nt][2] = __expf(sacc[mi][nt][2] - mn1);
                sacc[mi][nt][3] = __expf(sacc[mi][nt][3] - mn1);
                rs0 += sacc[mi][nt][0] + sacc[mi][nt][1];
                rs1 += sacc[mi][nt][2] + sacc[mi][nt][3];
            }
            rs0 += __shfl_xor_sync(0xffffffffu, rs0, 1);
            rs0 += __shfl_xor_sync(0xffffffffu, rs0, 2);
            rs1 += __shfl_xor_sync(0xffffffffu, rs1, 1);
            rs1 += __shfl_xor_sync(0xffffffffu, rs1, 2);

            lv[mi][0] = lv[mi][0] * corr0 + rs0;
            lv[mi][1] = lv[mi][1] * corr1 + rs1;
            #pragma unroll
            for (int nt = 0; nt < 8; nt++) {
                oacc[mi][nt][0] *= corr0; oacc[mi][nt][1] *= corr0;
                oacc[mi][nt][2] *= corr1; oacc[mi][nt][3] *= corr1;
            }

            // write P (accumulator layout) to warp-private smem rows
            const int rb = wq + mi * 16;
            #pragma unroll
            for (int nt = 0; nt < 8; nt++) {
                float2 p0 = make_float2(f2tf32(sacc[mi][nt][0]), f2tf32(sacc[mi][nt][1]));
                float2 p1 = make_float2(f2tf32(sacc[mi][nt][2]), f2tf32(sacc[mi][nt][3]));
                *(float2*)&Ps[(rb + r    ) * KP + nt * 8 + 2 * c] = p0;
                *(float2*)&Ps[(rb + r + 8) * KP + nt * 8 + 2 * c] = p1;
            }
        }
        __syncwarp();   // P rows warp-private

        // ---- O += P·V : B frags shared by both m-frags ----
        #pragma unroll
        for (int kk = 0; kk < 8; kk++) {
            const int kb = kk * 8;
            float af[2][4];
            #pragma unroll
            for (int mi = 0; mi < 2; mi++) {
                const int rb = wq + mi * 16;
                af[mi][0] = Ps[(rb + r    ) * KP + kb + c    ];
                af[mi][1] = Ps[(rb + r + 8) * KP + kb + c    ];
                af[mi][2] = Ps[(rb + r    ) * KP + kb + c + 4];
                af[mi][3] = Ps[(rb + r + 8) * KP + kb + c + 4];
            }
            #pragma unroll
            for (int nt = 0; nt < 8; nt++) {
                float b0 = Vs[(kb + c    ) * VP + nt * 8 + r];
                float b1 = Vs[(kb + c + 4) * VP + nt * 8 + r];
                #pragma unroll
                for (int mi = 0; mi < 2; mi++)
                    mma_tf32(oacc[mi][nt][0], oacc[mi][nt][1], oacc[mi][nt][2], oacc[mi][nt][3],
                             af[mi][0], af[mi][1], af[mi][2], af[mi][3], b0, b1);
            }
        }
    }

    // ---- normalize and write context ----
    #pragma unroll
    for (int mi = 0; mi < 2; mi++) {
        const float inv0 = 1.0f / lv[mi][0];
        const float inv1 = 1.0f / lv[mi][1];
        const int rb = wq + mi * 16;
        #pragma unroll
        for (int nt = 0; nt < 8; nt++) {
            const int col = nt * 8 + 2 * c;
            float2 o0 = make_float2(oacc[mi][nt][0] * inv0, oacc[mi][nt][1] * inv0);
            float2 o1 = make_float2(oacc[mi][nt][2] * inv1, oacc[mi][nt][3] * inv1);
            *(float2*)(O + base + (size_t)(q0 + rb + r    ) * D_MODEL + col) = o0;
            *(float2*)(O + base + (size_t)(q0 + rb + r + 8) * D_MODEL + col) = o1;
        }
    }
}

// ---------------------------------------------------------------------------
// Launch: merged QKV projection -> attention -> output projection
// Inputs (metadata order): x1, x2, Wq, bq, Wk, bk, Wv, bv, Wo, bo
// ---------------------------------------------------------------------------
extern "C" void kernel_launch(void* const* d_in, const int* in_sizes, int n_in,
                              void* d_out, int out_size)
{
    (void)in_sizes; (void)n_in; (void)out_size;

    const float* x1 = (const float*)d_in[0];
    const float* x2 = (const float*)d_in[1];
    const float* Wq = (const float*)d_in[2];
    const float* bq = (const float*)d_in[3];
    const float* Wk = (const float*)d_in[4];
    const float* bk = (const float*)d_in[5];
    const float* Wv = (const float*)d_in[6];
    const float* bv = (const float*)d_in[7];
    const float* Wo = (const float*)d_in[8];
    const float* bo = (const float*)d_in[9];
    float* out = (float*)d_out;

    float *Qp, *Kp, *Vp, *Cp;
    cudaGetSymbolAddress((void**)&Qp, g_Q);
    cudaGetSymbolAddress((void**)&Kp, g_K);
    cudaGetSymbolAddress((void**)&Vp, g_V);
    cudaGetSymbolAddress((void**)&Cp, g_C);

    const int gemm_smem = GEMM_SMEM_FLOATS * (int)sizeof(float);   // 74752 B
    cudaFuncSetAttribute(qkv_gemm_kernel,
                         cudaFuncAttributeMaxDynamicSharedMemorySize, gemm_smem);
    cudaFuncSetAttribute(out_gemm_kernel,
                         cudaFuncAttributeMaxDynamicSharedMemorySize, gemm_smem);

    const int attn_smem = ATTN_SMEM_FLOATS * (int)sizeof(float);   // 105472 B
    cudaFuncSetAttribute(attn_mma_kernel,
                         cudaFuncAttributeMaxDynamicSharedMemorySize, attn_smem);

    dim3 qkv_grid(GEMM_N / 128, GEMM_M / 128, 3);   // (8, 32, 3)
    qkv_gemm_kernel<<<qkv_grid, 128, gemm_smem>>>(x1, x2, Wq, bq, Wk, bk, Wv, bv,
                                                  Qp, Kp, Vp);

    dim3 attn_grid(SEQ / QT, NUM_HEADS, B_SZ);      // (16, 16, 2)
    attn_mma_kernel<<<attn_grid, 128, attn_smem>>>(Qp, Kp, Vp, Cp);

    dim3 out_grid(GEMM_N / 128, GEMM_M / 128);      // (8, 32)
    out_gemm_kernel<<<out_grid, 128, gemm_smem>>>(Cp, Wo, bo, out);
}

// round 13
// speedup vs baseline: 1.4126x; 1.0250x over previous
#include <cuda_runtime.h>
#include <cstdint>
#include <cmath>

// Problem constants (fixed by the reference)
#define D_MODEL   1024
#define NUM_HEADS 16
#define HEAD_DIM  64
#define B_SZ      2
#define SEQ       2048
#define M_TOT     (B_SZ * SEQ)   // 4096 rows for all projection GEMMs

// Scratch (allocation-free rule: __device__ globals). 4 x 16 MB = 64 MB.
__device__ float g_Q[(size_t)M_TOT * D_MODEL];
__device__ float g_K[(size_t)M_TOT * D_MODEL];
__device__ float g_V[(size_t)M_TOT * D_MODEL];
__device__ float g_C[(size_t)M_TOT * D_MODEL];

// ---------------------------------------------------------------------------
// tf32 / cp.async helpers
// ---------------------------------------------------------------------------
__device__ __forceinline__ float f2tf32(float x) {
    asm("cvt.rna.tf32.f32 %0, %0;" : "+f"(x));
    return x;
}

__device__ __forceinline__ void mma_tf32(float& c0, float& c1, float& c2, float& c3,
                                         float a0, float a1, float a2, float a3,
                                         float b0, float b1)
{
    asm volatile(
        "mma.sync.aligned.m16n8k8.row.col.f32.tf32.tf32.f32 "
        "{%0,%1,%2,%3}, {%4,%5,%6,%7}, {%8,%9}, {%0,%1,%2,%3};\n"
        : "+f"(c0), "+f"(c1), "+f"(c2), "+f"(c3)
        : "r"(__float_as_uint(a0)), "r"(__float_as_uint(a1)),
          "r"(__float_as_uint(a2)), "r"(__float_as_uint(a3)),
          "r"(__float_as_uint(b0)), "r"(__float_as_uint(b1)));
}

__device__ __forceinline__ void cp_async16(uint32_t dst, const void* src) {
    asm volatile("cp.async.cg.shared.global [%0], [%1], 16;\n" :: "r"(dst), "l"(src));
}
#define CP_COMMIT() asm volatile("cp.async.commit_group;\n" ::: "memory")
#define CP_WAIT(n)  asm volatile("cp.async.wait_group %0;\n" :: "n"(n) : "memory")

// ---------------------------------------------------------------------------
// GEMM + bias (tf32 tensor cores, cp.async 3-stage pipeline, 3 CTAs/SM)
//   Y[4096,1024] = X[4096,1024] @ W[1024,1024] + b
// CTA tile 128x128, BK=16, 128 threads = 4 warps (2m x 2n), warp tile 64x64.
// NSTAGE=3 drops smem to 56 KB/CTA and launch_bounds(128,3) caps regs at 170
// so THREE CTAs fit per SM (12 warps = 3/SMSP) — attacks the latency-bound
// profile (issue 30%, occ 11.5%) seen at 2 CTAs/SM.
// A in natural [m][k], pitch 20 (banks 20r+c — conflict-free).
// B in [k][n], pitch 132 (banks 4c+r — conflict-free).
// ---------------------------------------------------------------------------
#define GEMM_M   4096
#define GEMM_N   1024
#define GEMM_K   1024
#define AP       20
#define BPITCH   132
#define A_STAGE  (128 * AP)     // 2560 floats
#define B_STAGE  (16 * BPITCH)  // 2112 floats
#define NSTAGE   3
#define GEMM_SMEM_FLOATS (NSTAGE * (A_STAGE + B_STAGE))   // 14016 -> 56064 B

__device__ __forceinline__ void gemm_issue_stage(
    uint32_t smem_u32, int s, int k0, int tid,
    const float* __restrict__ X, const float* __restrict__ W,
    int m0, int n0)
{
    // A: 128 rows x 16 k = 512 float4 slots; 4 per thread.
    #pragma unroll
    for (int i = 0; i < 4; i++) {
        const int idx = i * 128 + tid;        // 0..511
        const int m   = idx >> 2;             // 0..127
        const int ko  = (idx & 3) * 4;        // 0,4,8,12
        const float* src = X + (size_t)(m0 + m) * GEMM_K + k0 + ko;
        uint32_t dst = smem_u32 + (uint32_t)((s * A_STAGE + m * AP + ko) * 4);
        cp_async16(dst, src);
    }
    // B: 16 k-rows x 128 n = 512 float4 slots; 4 per thread.
    #pragma unroll
    for (int i = 0; i < 4; i++) {
        const int idx = i * 128 + tid;        // 0..511
        const int k   = idx >> 5;             // 0..15
        const int n4  = (idx & 31) * 4;       // 0..124
        const float* src = W + (size_t)(k0 + k) * GEMM_N + n0 + n4;
        uint32_t dst = smem_u32 +
            (uint32_t)((NSTAGE * A_STAGE + s * B_STAGE + k * BPITCH + n4) * 4);
        cp_async16(dst, src);
    }
}

__device__ __forceinline__ void gemm_body(
    const float* __restrict__ X, const float* __restrict__ W,
    const float* __restrict__ bias, float* __restrict__ Y)
{
    extern __shared__ __align__(16) float gsm[];
    uint32_t smem_u32 = (uint32_t)__cvta_generic_to_shared(gsm);

    const int tid  = threadIdx.x;
    const int lane = tid & 31;
    const int warp = tid >> 5;           // 0..3
    const int wm   = (warp >> 1) * 64;   // warp m offset
    const int wn   = (warp & 1) * 64;    // warp n offset
    const int r    = lane >> 2;
    const int c    = lane & 3;

    const int m0 = blockIdx.y * 128;
    const int n0 = blockIdx.x * 128;

    float acc[4][8][4];
    #pragma unroll
    for (int i = 0; i < 4; i++)
        #pragma unroll
        for (int j = 0; j < 8; j++)
            #pragma unroll
            for (int q = 0; q < 4; q++) acc[i][j][q] = 0.f;

    const int nIter = GEMM_K / 16;   // 64

    // prologue: stages 0..1 in flight
    #pragma unroll
    for (int s = 0; s < NSTAGE - 1; s++) {
        gemm_issue_stage(smem_u32, s, s * 16, tid, X, W, m0, n0);
        CP_COMMIT();
    }

    for (int it = 0; it < nIter; it++) {
        CP_WAIT(NSTAGE - 2);      // stage `it` landed
        __syncthreads();          // ...for every thread; prev buf fully consumed

        if (it + NSTAGE - 1 < nIter)
            gemm_issue_stage(smem_u32, (it + NSTAGE - 1) % NSTAGE,
                             (it + NSTAGE - 1) * 16, tid, X, W, m0, n0);
        CP_COMMIT();              // one group per iteration (may be empty)

        const int buf = it % NSTAGE;
        const float* Ab = gsm + buf * A_STAGE;
        const float* Bb = gsm + NSTAGE * A_STAGE + buf * B_STAGE;

        #pragma unroll
        for (int s = 0; s < 2; s++) {
            const int kb = s * 8;
            float af[4][4], bf[8][2];
            #pragma unroll
            for (int mi = 0; mi < 4; mi++) {
                const int mb = wm + 16 * mi;
                af[mi][0] = f2tf32(Ab[(mb + r    ) * AP + kb + c    ]);
                af[mi][1] = f2tf32(Ab[(mb + r + 8) * AP + kb + c    ]);
                af[mi][2] = f2tf32(Ab[(mb + r    ) * AP + kb + c + 4]);
                af[mi][3] = f2tf32(Ab[(mb + r + 8) * AP + kb + c + 4]);
            }
            #pragma unroll
            for (int ni = 0; ni < 8; ni++) {
                const int nb = wn + 8 * ni;
                bf[ni][0] = f2tf32(Bb[(kb + c    ) * BPITCH + nb + r]);
                bf[ni][1] = f2tf32(Bb[(kb + c + 4) * BPITCH + nb + r]);
            }
            #pragma unroll
            for (int mi = 0; mi < 4; mi++)
                #pragma unroll
                for (int ni = 0; ni < 8; ni++)
                    mma_tf32(acc[mi][ni][0], acc[mi][ni][1], acc[mi][ni][2], acc[mi][ni][3],
                             af[mi][0], af[mi][1], af[mi][2], af[mi][3],
                             bf[ni][0], bf[ni][1]);
        }
    }

    // epilogue: add bias, write. c-frag layout: rows r, r+8; cols 2c, 2c+1.
    #pragma unroll
    for (int mi = 0; mi < 4; mi++) {
        const int m = m0 + wm + 16 * mi + r;
        #pragma unroll
        for (int ni = 0; ni < 8; ni++) {
            const int n = n0 + wn + 8 * ni + 2 * c;
            const float bx = bias[n], by = bias[n + 1];
            float2 o0 = make_float2(acc[mi][ni][0] + bx, acc[mi][ni][1] + by);
            float2 o1 = make_float2(acc[mi][ni][2] + bx, acc[mi][ni][3] + by);
            *(float2*)(Y + (size_t)m * GEMM_N + n)       = o0;
            *(float2*)(Y + (size_t)(m + 8) * GEMM_N + n) = o1;
        }
    }
}

// Merged Q/K/V projection: blockIdx.z selects which projection this CTA does.
__global__ __launch_bounds__(128, 3) void qkv_gemm_kernel(
    const float* __restrict__ x1, const float* __restrict__ x2,
    const float* __restrict__ Wq, const float* __restrict__ bq,
    const float* __restrict__ Wk, const float* __restrict__ bk,
    const float* __restrict__ Wv, const float* __restrict__ bv,
    float* __restrict__ Qp, float* __restrict__ Kp, float* __restrict__ Vp)
{
    const float *X, *W, *bias;
    float* Y;
    if (blockIdx.z == 0)      { X = x1; W = Wq; bias = bq; Y = Qp; }
    else if (blockIdx.z == 1) { X = x2; W = Wk; bias = bk; Y = Kp; }
    else                      { X = x2; W = Wv; bias = bv; Y = Vp; }
    gemm_body(X, W, bias, Y);
}

__global__ __launch_bounds__(128, 3) void out_gemm_kernel(
    const float* __restrict__ X, const float* __restrict__ W,
    const float* __restrict__ bias, float* __restrict__ Y)
{
    gemm_body(X, W, bias, Y);
}

// ---------------------------------------------------------------------------
// Flash attention with tf32 tensor cores — FA2 warp shape (proven, R8).
// CTA = (b, h, 128-row Q tile). 128 threads = 4 warps; warp w owns Q rows
// [w*32, w*32+32) as TWO m16 A-fragments.
// ---------------------------------------------------------------------------
#define QT      128
#define KTILE   64
#define KP      68
#define VP      72
#define ATTN_SMEM_FLOATS (QT * KP + QT * KP + KTILE * KP + KTILE * VP)

__global__ __launch_bounds__(128, 2) void attn_mma_kernel(
    const float* __restrict__ Q, const float* __restrict__ K,
    const float* __restrict__ V, float* __restrict__ O)
{
    extern __shared__ float sm[];
    float* Qs = sm;                       // [128][KP]
    float* Ps = Qs + QT * KP;             // [128][KP]
    float* Ks = Ps + QT * KP;             // [64][KP]
    float* Vs = Ks + KTILE * KP;          // [64][VP]

    const int tid  = threadIdx.x;
    const int lane = tid & 31;
    const int warp = tid >> 5;    // 0..3
    const int r    = lane >> 2;   // fragment row group 0..7
    const int c    = lane & 3;    // fragment k/col group 0..3
    const int wq   = warp * 32;   // warp's 32-row Q strip

    const int q0 = blockIdx.x * QT;
    const int h  = blockIdx.y;
    const int b  = blockIdx.z;
    const size_t base = (size_t)b * SEQ * D_MODEL + (size_t)h * HEAD_DIM;

    // ---- load Q tile (128 x 64) -> Qs (tf32) ----
    #pragma unroll
    for (int i = 0; i < 16; i++) {
        const int idx  = i * 128 + tid;       // 2048 float4 slots
        const int row  = idx >> 4;            // 0..127
        const int col4 = (idx & 15) * 4;      // 0..60
        float4 v = *(const float4*)(Q + base + (size_t)(q0 + row) * D_MODEL + col4);
        Qs[row * KP + col4 + 0] = f2tf32(v.x);
        Qs[row * KP + col4 + 1] = f2tf32(v.y);
        Qs[row * KP + col4 + 2] = f2tf32(v.z);
        Qs[row * KP + col4 + 3] = f2tf32(v.w);
    }

    float oacc[2][8][4];
    float mv[2][2], lv[2][2];
    #pragma unroll
    for (int mi = 0; mi < 2; mi++) {
        mv[mi][0] = -1e30f; mv[mi][1] = -1e30f;
        lv[mi][0] = 0.f;    lv[mi][1] = 0.f;
        #pragma unroll
        for (int i = 0; i < 8; i++)
            #pragma unroll
            for (int j = 0; j < 4; j++) oacc[mi][i][j] = 0.f;
    }

    const float scale = 0.125f;   // 1/sqrt(64)

    for (int kt = 0; kt < SEQ / KTILE; kt++) {
        __syncthreads();   // previous iteration's consumers of Ks/Vs done

        // ---- load K,V tiles (64 x 64 each) -> smem (tf32) ----
        #pragma unroll
        for (int i = 0; i < 8; i++) {
            const int idx  = i * 128 + tid;       // 1024 float4 slots
            const int row  = idx >> 4;            // 0..63
            const int col4 = (idx & 15) * 4;
            const size_t g = base + (size_t)(kt * KTILE + row) * D_MODEL + col4;
            float4 kv = *(const float4*)(K + g);
            Ks[row * KP + col4 + 0] = f2tf32(kv.x);
            Ks[row * KP + col4 + 1] = f2tf32(kv.y);
            Ks[row * KP + col4 + 2] = f2tf32(kv.z);
            Ks[row * KP + col4 + 3] = f2tf32(kv.w);
            float4 vv = *(const float4*)(V + g);
            Vs[row * VP + col4 + 0] = f2tf32(vv.x);
            Vs[row * VP + col4 + 1] = f2tf32(vv.y);
            Vs[row * VP + col4 + 2] = f2tf32(vv.z);
            Vs[row * VP + col4 + 3] = f2tf32(vv.w);
        }
        __syncthreads();

        // ---- S = Q·K^T : 32 x 64 per warp; B frags shared by both m-frags ----
        float sacc[2][8][4];
        #pragma unroll
        for (int mi = 0; mi < 2; mi++)
            #pragma unroll
            for (int i = 0; i < 8; i++)
                #pragma unroll
                for (int j = 0; j < 4; j++) sacc[mi][i][j] = 0.f;

        #pragma unroll
        for (int kk = 0; kk < 8; kk++) {
            const int kb = kk * 8;
            float af[2][4];
            #pragma unroll
            for (int mi = 0; mi < 2; mi++) {
                const int rb = wq + mi * 16;
                af[mi][0] = Qs[(rb + r    ) * KP + kb + c    ];
                af[mi][1] = Qs[(rb + r + 8) * KP + kb + c    ];
                af[mi][2] = Qs[(rb + r    ) * KP + kb + c + 4];
                af[mi][3] = Qs[(rb + r + 8) * KP + kb + c + 4];
            }
            #pragma unroll
            for (int nt = 0; nt < 8; nt++) {
                float b0 = Ks[(nt * 8 + r) * KP + kb + c    ];
                float b1 = Ks[(nt * 8 + r) * KP + kb + c + 4];
                #pragma unroll
                for (int mi = 0; mi < 2; mi++)
                    mma_tf32(sacc[mi][nt][0], sacc[mi][nt][1], sacc[mi][nt][2], sacc[mi][nt][3],
                             af[mi][0], af[mi][1], af[mi][2], af[mi][3], b0, b1);
            }
        }

        // ---- online softmax per m-frag (rows r and r+8 within each) ----
        #pragma unroll
        for (int mi = 0; mi < 2; mi++) {
            float mx0 = -1e30f, mx1 = -1e30f;
            #pragma unroll
            for (int nt = 0; nt < 8; nt++) {
                sacc[mi][nt][0] *= scale; sacc[mi][nt][1] *= scale;
                sacc[mi][nt][2] *= scale; sacc[mi][nt][3] *= scale;
                mx0 = fmaxf(mx0, fmaxf(sacc[mi][nt][0], sacc[mi][nt][1]));
                mx1 = fmaxf(mx1, fmaxf(sacc[mi][nt][2], sacc[mi][nt][3]));
            }
            mx0 = fmaxf(mx0, __shfl_xor_sync(0xffffffffu, mx0, 1));
            mx0 = fmaxf(mx0, __shfl_xor_sync(0xffffffffu, mx0, 2));
            mx1 = fmaxf(mx1, __shfl_xor_sync(0xffffffffu, mx1, 1));
            mx1 = fmaxf(mx1, __shfl_xor_sync(0xffffffffu, mx1, 2));

            const float mn0 = fmaxf(mv[mi][0], mx0);
            const float mn1 = fmaxf(mv[mi][1], mx1);
            const float corr0 = __expf(mv[mi][0] - mn0);
            const float corr1 = __expf(mv[mi][1] - mn1);
            mv[mi][0] = mn0; mv[mi][1] = mn1;

            float rs0 = 0.f, rs1 = 0.f;
            #pragma unroll
            for (int nt = 0; nt < 8; nt++) {
                sacc[mi][nt][0] = __expf(sacc[mi][nt][0] - mn0);
                sacc[mi][nt][1] = __expf(sacc[mi][nt][1] - mn0);
                sacc[mi][nt][2] = __expf(sacc[mi][nt][2] - mn1);
                sacc[mi][nt][3] = __expf(sacc[mi][nt][3] - mn1);
                rs0 += sacc[mi][nt][0] + sacc[mi][nt][1];
                rs1 += sacc[mi][nt][2] + sacc[mi][nt][3];
            }
            rs0 += __shfl_xor_sync(0xffffffffu, rs0, 1);
            rs0 += __shfl_xor_sync(0xffffffffu, rs0, 2);
            rs1 += __shfl_xor_sync(0xffffffffu, rs1, 1);
            rs1 += __shfl_xor_sync(0xffffffffu, rs1, 2);

            lv[mi][0] = lv[mi][0] * corr0 + rs0;
            lv[mi][1] = lv[mi][1] * corr1 + rs1;
            #pragma unroll
            for (int nt = 0; nt < 8; nt++) {
                oacc[mi][nt][0] *= corr0; oacc[mi][nt][1] *= corr0;
                oacc[mi][nt][2] *= corr1; oacc[mi][nt][3] *= corr1;
            }

            // write P (accumulator layout) to warp-private smem rows
            const int rb = wq + mi * 16;
            #pragma unroll
            for (int nt = 0; nt < 8; nt++) {
                float2 p0 = make_float2(f2tf32(sacc[mi][nt][0]), f2tf32(sacc[mi][nt][1]));
                float2 p1 = make_float2(f2tf32(sacc[mi][nt][2]), f2tf32(sacc[mi][nt][3]));
                *(float2*)&Ps[(rb + r    ) * KP + nt * 8 + 2 * c] = p0;
                *(float2*)&Ps[(rb + r + 8) * KP + nt * 8 + 2 * c] = p1;
            }
        }
        __syncwarp();   // P rows warp-private

        // ---- O += P·V : B frags shared by both m-frags ----
        #pragma unroll
        for (int kk = 0; kk < 8; kk++) {
            const int kb = kk * 8;
            float af[2][4];
            #pragma unroll
            for (int mi = 0; mi < 2; mi++) {
                const int rb = wq + mi * 16;
                af[mi][0] = Ps[(rb + r    ) * KP + kb + c    ];
                af[mi][1] = Ps[(rb + r + 8) * KP + kb + c    ];
                af[mi][2] = Ps[(rb + r    ) * KP + kb + c + 4];
                af[mi][3] = Ps[(rb + r + 8) * KP + kb + c + 4];
            }
            #pragma unroll
            for (int nt = 0; nt < 8; nt++) {
                float b0 = Vs[(kb + c    ) * VP + nt * 8 + r];
                float b1 = Vs[(kb + c + 4) * VP + nt * 8 + r];
                #pragma unroll
                for (int mi = 0; mi < 2; mi++)
                    mma_tf32(oacc[mi][nt][0], oacc[mi][nt][1], oacc[mi][nt][2], oacc[mi][nt][3],
                             af[mi][0], af[mi][1], af[mi][2], af[mi][3], b0, b1);
            }
        }
    }

    // ---- normalize and write context ----
    #pragma unroll
    for (int mi = 0; mi < 2; mi++) {
        const float inv0 = 1.0f / lv[mi][0];
        const float inv1 = 1.0f / lv[mi][1];
        const int rb = wq + mi * 16;
        #pragma unroll
        for (int nt = 0; nt < 8; nt++) {
            const int col = nt * 8 + 2 * c;
            float2 o0 = make_float2(oacc[mi][nt][0] * inv0, oacc[mi][nt][1] * inv0);
            float2 o1 = make_float2(oacc[mi][nt][2] * inv1, oacc[mi][nt][3] * inv1);
            *(float2*)(O + base + (size_t)(q0 + rb + r    ) * D_MODEL + col) = o0;
            *(float2*)(O + base + (size_t)(q0 + rb + r + 8) * D_MODEL + col) = o1;
        }
    }
}

// ---------------------------------------------------------------------------
// Launch: merged QKV projection -> attention -> output projection
// Inputs (metadata order): x1, x2, Wq, bq, Wk, bk, Wv, bv, Wo, bo
// ---------------------------------------------------------------------------
extern "C" void kernel_launch(void* const* d_in, const int* in_sizes, int n_in,
                              void* d_out, int out_size)
{
    (void)in_sizes; (void)n_in; (void)out_size;

    const float* x1 = (const float*)d_in[0];
    const float* x2 = (const float*)d_in[1];
    const float* Wq = (const float*)d_in[2];
    const float* bq = (const float*)d_in[3];
    const float* Wk = (const float*)d_in[4];
    const float* bk = (const float*)d_in[5];
    const float* Wv = (const float*)d_in[6];
    const float* bv = (const float*)d_in[7];
    const float* Wo = (const float*)d_in[8];
    const float* bo = (const float*)d_in[9];
    float* out = (float*)d_out;

    float *Qp, *Kp, *Vp, *Cp;
    cudaGetSymbolAddress((void**)&Qp, g_Q);
    cudaGetSymbolAddress((void**)&Kp, g_K);
    cudaGetSymbolAddress((void**)&Vp, g_V);
    cudaGetSymbolAddress((void**)&Cp, g_C);

    const int gemm_smem = GEMM_SMEM_FLOATS * (int)sizeof(float);   // 56064 B
    cudaFuncSetAttribute(qkv_gemm_kernel,
                         cudaFuncAttributeMaxDynamicSharedMemorySize, gemm_smem);
    cudaFuncSetAttribute(out_gemm_kernel,
                         cudaFuncAttributeMaxDynamicSharedMemorySize, gemm_smem);

    const int attn_smem = ATTN_SMEM_FLOATS * (int)sizeof(float);   // 105472 B
    cudaFuncSetAttribute(attn_mma_kernel,
                         cudaFuncAttributeMaxDynamicSharedMemorySize, attn_smem);

    dim3 qkv_grid(GEMM_N / 128, GEMM_M / 128, 3);   // (8, 32, 3)
    qkv_gemm_kernel<<<qkv_grid, 128, gemm_smem>>>(x1, x2, Wq, bq, Wk, bk, Wv, bv,
                                                  Qp, Kp, Vp);

    dim3 attn_grid(SEQ / QT, NUM_HEADS, B_SZ);      // (16, 16, 2)
    attn_mma_kernel<<<attn_grid, 128, attn_smem>>>(Qp, Kp, Vp, Cp);

    dim3 out_grid(GEMM_N / 128, GEMM_M / 128);      // (8, 32)
    out_gemm_kernel<<<out_grid, 128, gemm_smem>>>(Cp, Wo, bo, out);
}